// round 9
// baseline (speedup 1.0000x reference)
#include <cuda_runtime.h>
#include <cuda_bf16.h>
#include <math.h>
#include <stdint.h>

#define BB   2
#define TT   2048
#define NXC  512
#define HD   128
#define LL   64
#define KK   32
#define EPSC 1e-5f

// ---------------- device scratch ----------------
__device__ float g_v[BB*TT*NXC];
__device__ float g_w1 [BB*4*TT*LL];
__device__ float g_w2T[BB*4*TT*LL];
__device__ float g_vmean[BB*NXC];
__device__ int   g_cnt [BB*TT];
__device__ int   g_rows[BB*TT*KK];
__device__ float g_lam, g_lam_init;
__device__ __nv_bfloat16 g_xh[BB*TT*NXC];
__device__ __nv_bfloat16 g_xl[BB*TT*NXC];
__device__ __nv_bfloat16 g_wh[4*NXC*NXC];
__device__ __nv_bfloat16 g_wl[4*NXC*NXC];
__device__ __nv_bfloat16 g_ah[BB*TT*NXC];
__device__ __nv_bfloat16 g_al[BB*TT*NXC];
// q,k stored as bf16 hi/lo (head0 columns dead but kept for layout)
__device__ __nv_bfloat16 g_qh[BB*TT*NXC];
__device__ __nv_bfloat16 g_ql[BB*TT*NXC];
__device__ __nv_bfloat16 g_kh[BB*TT*NXC];
__device__ __nv_bfloat16 g_kl[BB*TT*NXC];
// landmark matrices bf16 hi/lo [bh][l][d]
__device__ __nv_bfloat16 g_sqh[8*LL*HD], g_sql[8*LL*HD];
__device__ __nv_bfloat16 g_skh[8*LL*HD], g_skl[8*LL*HD];
__device__ unsigned g_bits[BB*TT*(TT/32)];

__device__ __forceinline__ uint32_t smem_u32(const void* p) {
    uint32_t a;
    asm("{ .reg .u64 t; cvta.to.shared.u64 t, %1; cvt.u32.u64 %0, t; }" : "=r"(a) : "l"(p));
    return a;
}
#define CP16(dst, src) \
    asm volatile("cp.async.cg.shared.global [%0], [%1], 16;" :: "r"(dst), "l"(src))
#define MMA_BF16(acc, a, b) \
    asm volatile("mma.sync.aligned.m16n8k16.row.col.f32.bf16.bf16.f32 " \
        "{%0,%1,%2,%3}, {%4,%5,%6,%7}, {%8,%9}, {%0,%1,%2,%3};" \
        : "+f"((acc)[0]), "+f"((acc)[1]), "+f"((acc)[2]), "+f"((acc)[3]) \
        : "r"((a)[0]), "r"((a)[1]), "r"((a)[2]), "r"((a)[3]), "r"((b)[0]), "r"((b)[1]))

// ============ HMMA split-bf16 GEMM, cp.async double-buffered, persistent ===
#define SST  40
#define MATB (128*SST*2)
#define BUFB (4*MATB)
#define SMEMB (2*BUFB)
__global__ void __launch_bounds__(256, 1) k_mma(int mode, float* __restrict__ outp)
{
    extern __shared__ __align__(16) char dsm[];
    const int tid = threadIdx.x, lane = tid & 31, wid = tid >> 5;
    const uint32_t sbase = smem_u32(dsm);
    const int ntiles = (mode == 0) ? 320 : 128;

    const int lr = tid >> 2, lq = tid & 3;
    const uint32_t so  = (uint32_t)(lr * SST + lq * 8) * 2;
    const uint32_t so2 = so + 64 * SST * 2;

    const int wm = (wid >> 2) * 64;
    const int wn = (wid & 3) * 32;
    uint32_t aoff[4], boff[4];
    {
        int arow = wm + (lane & 15);
        int acol = ((lane >> 4) & 1) * 8;
        #pragma unroll
        for (int mi = 0; mi < 4; mi++)
            aoff[mi] = (uint32_t)((arow + mi * 16) * SST + acol) * 2;
        int l15 = lane & 15;
        int brow = wn + (l15 & 7);
        int bcol = ((l15 >> 3) & 1) * 8;
        #pragma unroll
        for (int ni = 0; ni < 4; ni++)
            boff[ni] = (uint32_t)((brow + ni * 8) * SST + bcol) * 2;
    }

    const __nv_bfloat16* Abase_h = (mode == 0) ? g_xh : g_ah;
    const __nv_bfloat16* Abase_l = (mode == 0) ? g_xl : g_al;

    for (int t = blockIdx.x; t < ntiles; t += gridDim.x) {
        int z, mb, nb;
        if (mode == 0) {
            if (t < 192) { z = t / 96; int r = t % 96; nb = r % 3 + 1; mb = r / 3; }
            else         { z = 2; int r = t - 192; nb = r & 3; mb = r >> 2; }
        } else { z = 3; nb = t & 3; mb = t >> 2; }
        const int m0 = mb * 128, n0 = nb * 128;
        const __nv_bfloat16* Bh = g_wh + (size_t)z * NXC * NXC;
        const __nv_bfloat16* Bl = g_wl + (size_t)z * NXC * NXC;

        const size_t gA0 = (size_t)(m0 + lr) * NXC + lq * 8;
        const size_t gA1 = gA0 + (size_t)64 * NXC;
        const size_t gB0 = (size_t)(n0 + lr) * NXC + lq * 8;
        const size_t gB1 = gB0 + (size_t)64 * NXC;

        auto issue = [&](int ch, int p) {
            uint32_t s0 = sbase + (uint32_t)p * BUFB;
            int ko = ch * 32;
            CP16(s0 + so,           Abase_h + gA0 + ko);
            CP16(s0 + so2,          Abase_h + gA1 + ko);
            CP16(s0 + MATB + so,    Abase_l + gA0 + ko);
            CP16(s0 + MATB + so2,   Abase_l + gA1 + ko);
            CP16(s0 + 2*MATB + so,  Bh + gB0 + ko);
            CP16(s0 + 2*MATB + so2, Bh + gB1 + ko);
            CP16(s0 + 3*MATB + so,  Bl + gB0 + ko);
            CP16(s0 + 3*MATB + so2, Bl + gB1 + ko);
            asm volatile("cp.async.commit_group;" ::: "memory");
        };

        float acc[4][4][4];
        #pragma unroll
        for (int a = 0; a < 4; a++)
            #pragma unroll
            for (int b = 0; b < 4; b++)
                #pragma unroll
                for (int c = 0; c < 4; c++) acc[a][b][c] = 0.f;

        issue(0, 0);
        for (int ch = 0; ch < 16; ch++) {
            if (ch + 1 < 16) {
                issue(ch + 1, (ch + 1) & 1);
                asm volatile("cp.async.wait_group 1;" ::: "memory");
            } else {
                asm volatile("cp.async.wait_group 0;" ::: "memory");
            }
            __syncthreads();

            uint32_t mb_ = sbase + (uint32_t)(ch & 1) * BUFB;
            #pragma unroll
            for (int kk = 0; kk < 2; kk++) {
                uint32_t koff = (uint32_t)kk * 32;
                uint32_t aH[4][4], aL[4][4], bH[4][2], bL[4][2];
                #pragma unroll
                for (int mi = 0; mi < 4; mi++)
                    asm volatile("ldmatrix.sync.aligned.m8n8.x4.shared.b16 {%0,%1,%2,%3}, [%4];"
                        : "=r"(aH[mi][0]), "=r"(aH[mi][1]), "=r"(aH[mi][2]), "=r"(aH[mi][3])
                        : "r"(mb_ + aoff[mi] + koff));
                #pragma unroll
                for (int mi = 0; mi < 4; mi++)
                    asm volatile("ldmatrix.sync.aligned.m8n8.x4.shared.b16 {%0,%1,%2,%3}, [%4];"
                        : "=r"(aL[mi][0]), "=r"(aL[mi][1]), "=r"(aL[mi][2]), "=r"(aL[mi][3])
                        : "r"(mb_ + MATB + aoff[mi] + koff));
                #pragma unroll
                for (int ni = 0; ni < 4; ni++)
                    asm volatile("ldmatrix.sync.aligned.m8n8.x2.shared.b16 {%0,%1}, [%2];"
                        : "=r"(bH[ni][0]), "=r"(bH[ni][1])
                        : "r"(mb_ + 2*MATB + boff[ni] + koff));
                #pragma unroll
                for (int ni = 0; ni < 4; ni++)
                    asm volatile("ldmatrix.sync.aligned.m8n8.x2.shared.b16 {%0,%1}, [%2];"
                        : "=r"(bL[ni][0]), "=r"(bL[ni][1])
                        : "r"(mb_ + 3*MATB + boff[ni] + koff));
                #pragma unroll
                for (int mi = 0; mi < 4; mi++)
                    #pragma unroll
                    for (int ni = 0; ni < 4; ni++) {
                        MMA_BF16(acc[mi][ni], aH[mi], bH[ni]);
                        MMA_BF16(acc[mi][ni], aH[mi], bL[ni]);
                        MMA_BF16(acc[mi][ni], aL[mi], bH[ni]);
                    }
            }
            __syncthreads();
        }

        const int er = lane >> 2, ec = (lane & 3) * 2;
        if (mode == 0 && z < 2) {
            __nv_bfloat16* H = z ? g_kh : g_qh;
            __nv_bfloat16* L = z ? g_kl : g_ql;
            #pragma unroll
            for (int mi = 0; mi < 4; mi++)
                #pragma unroll
                for (int ni = 0; ni < 4; ni++)
                    #pragma unroll
                    for (int half = 0; half < 2; half++) {
                        size_t row = (size_t)(m0 + wm + mi * 16 + er + half * 8);
                        size_t col = (size_t)(n0 + wn + ni * 8 + ec);
                        float v0 = acc[mi][ni][half*2], v1 = acc[mi][ni][half*2+1];
                        __nv_bfloat16 h0 = __float2bfloat16(v0);
                        __nv_bfloat16 h1 = __float2bfloat16(v1);
                        *(__nv_bfloat162*)(H + row * NXC + col) = __nv_bfloat162(h0, h1);
                        *(__nv_bfloat162*)(L + row * NXC + col) = __nv_bfloat162(
                            __float2bfloat16(v0 - __bfloat162float(h0)),
                            __float2bfloat16(v1 - __bfloat162float(h1)));
                    }
        } else {
            float* C = (mode == 0) ? g_v : outp;
            #pragma unroll
            for (int mi = 0; mi < 4; mi++)
                #pragma unroll
                for (int ni = 0; ni < 4; ni++) {
                    size_t row = (size_t)(m0 + wm + mi * 16 + er);
                    size_t col = (size_t)(n0 + wn + ni * 8 + ec);
                    *(float2*)(C + row * NXC + col) =
                        make_float2(acc[mi][ni][0], acc[mi][ni][1]);
                    *(float2*)(C + (row + 8) * NXC + col) =
                        make_float2(acc[mi][ni][2], acc[mi][ni][3]);
                }
        }
    }
}

// ============ HMMA w1/w2T: 12 gemms M=2048 N=64 K=128, heads 1..3 =========
// tile 128x64, 8 warps (2m x 4n), warp 64x16. 192 tiles.
#define W_AB (128*SST*2)        // 10240
#define W_BB (64*SST*2)         // 5120
#define W_STG (2*W_AB + 2*W_BB) // 30720
#define W_SMEM (2*W_STG)        // 61440
__global__ void __launch_bounds__(256, 1) k_w12m()
{
    extern __shared__ __align__(16) char dsm[];
    const int tid = threadIdx.x, lane = tid & 31, wid = tid >> 5;
    const uint32_t sbase = smem_u32(dsm);

    int t = blockIdx.x;
    int g = t >> 4, mb = t & 15;
    int isw2 = (g >= 6);
    if (isw2) g -= 6;
    int b = g / 3, h = g % 3 + 1, bh = b * 4 + h;
    const __nv_bfloat16* AH = isw2 ? g_kh : g_qh;
    const __nv_bfloat16* AL = isw2 ? g_kl : g_ql;
    const __nv_bfloat16* BH = (isw2 ? g_sqh : g_skh) + (size_t)bh * LL * HD;
    const __nv_bfloat16* BL = (isw2 ? g_sql : g_skl) + (size_t)bh * LL * HD;
    float* C = (isw2 ? g_w2T : g_w1) + (size_t)bh * TT * LL;

    const int lr = tid >> 2, lq = tid & 3;
    const uint32_t soA  = (uint32_t)(lr * SST + lq * 8) * 2;
    const uint32_t soA2 = soA + 64 * SST * 2;
    const size_t gA0 = (size_t)(b * TT + mb * 128 + lr) * NXC + h * HD + lq * 8;
    const size_t gA1 = gA0 + (size_t)64 * NXC;
    const size_t gB  = (size_t)lr * HD + lq * 8;   // lr in [0,64)

    const int wm = (wid >> 2) * 64;
    const int wn = (wid & 3) * 16;
    uint32_t aoff[4], boff[2];
    {
        int arow = wm + (lane & 15);
        int acol = ((lane >> 4) & 1) * 8;
        #pragma unroll
        for (int mi = 0; mi < 4; mi++)
            aoff[mi] = (uint32_t)((arow + mi * 16) * SST + acol) * 2;
        int l15 = lane & 15;
        int brow = wn + (l15 & 7);
        int bcol = ((l15 >> 3) & 1) * 8;
        #pragma unroll
        for (int ni = 0; ni < 2; ni++)
            boff[ni] = (uint32_t)((brow + ni * 8) * SST + bcol) * 2;
    }

    auto issue = [&](int ch, int p) {
        uint32_t s0 = sbase + (uint32_t)p * W_STG;
        int ko = ch * 32;
        CP16(s0 + soA,               AH + gA0 + ko);
        CP16(s0 + soA2,              AH + gA1 + ko);
        CP16(s0 + W_AB + soA,        AL + gA0 + ko);
        CP16(s0 + W_AB + soA2,       AL + gA1 + ko);
        CP16(s0 + 2*W_AB + soA,      BH + gB + ko);
        CP16(s0 + 2*W_AB + W_BB + soA, BL + gB + ko);
        asm volatile("cp.async.commit_group;" ::: "memory");
    };
    // NOTE: B loads use soA but only lr<64 rows exist; threads with lr>=64
    // would write past B region. Guard: B copy only for tid < 256 with lr<64.
    // (handled below by predicated variant)

    float acc[4][2][4];
    #pragma unroll
    for (int a = 0; a < 4; a++)
        #pragma unroll
        for (int b2 = 0; b2 < 2; b2++)
            #pragma unroll
            for (int c = 0; c < 4; c++) acc[a][b2][c] = 0.f;

    // B: 64 rows x 32 cols = 4KB per matrix -> 256 cp16 = 1 per thread (all lr<64 ok)
    // lr = tid>>2 in [0,64) since 256 threads -> fine, no guard needed.
    issue(0, 0);
    for (int ch = 0; ch < 4; ch++) {
        if (ch + 1 < 4) {
            issue(ch + 1, (ch + 1) & 1);
            asm volatile("cp.async.wait_group 1;" ::: "memory");
        } else {
            asm volatile("cp.async.wait_group 0;" ::: "memory");
        }
        __syncthreads();

        uint32_t mb_ = sbase + (uint32_t)(ch & 1) * W_STG;
        #pragma unroll
        for (int kk = 0; kk < 2; kk++) {
            uint32_t koff = (uint32_t)kk * 32;
            uint32_t aH[4][4], aL[4][4], bH[2][2], bL[2][2];
            #pragma unroll
            for (int mi = 0; mi < 4; mi++)
                asm volatile("ldmatrix.sync.aligned.m8n8.x4.shared.b16 {%0,%1,%2,%3}, [%4];"
                    : "=r"(aH[mi][0]), "=r"(aH[mi][1]), "=r"(aH[mi][2]), "=r"(aH[mi][3])
                    : "r"(mb_ + aoff[mi] + koff));
            #pragma unroll
            for (int mi = 0; mi < 4; mi++)
                asm volatile("ldmatrix.sync.aligned.m8n8.x4.shared.b16 {%0,%1,%2,%3}, [%4];"
                    : "=r"(aL[mi][0]), "=r"(aL[mi][1]), "=r"(aL[mi][2]), "=r"(aL[mi][3])
                    : "r"(mb_ + W_AB + aoff[mi] + koff));
            #pragma unroll
            for (int ni = 0; ni < 2; ni++)
                asm volatile("ldmatrix.sync.aligned.m8n8.x2.shared.b16 {%0,%1}, [%2];"
                    : "=r"(bH[ni][0]), "=r"(bH[ni][1])
                    : "r"(mb_ + 2*W_AB + boff[ni] + koff));
            #pragma unroll
            for (int ni = 0; ni < 2; ni++)
                asm volatile("ldmatrix.sync.aligned.m8n8.x2.shared.b16 {%0,%1}, [%2];"
                    : "=r"(bL[ni][0]), "=r"(bL[ni][1])
                    : "r"(mb_ + 2*W_AB + W_BB + boff[ni] + koff));
            #pragma unroll
            for (int mi = 0; mi < 4; mi++)
                #pragma unroll
                for (int ni = 0; ni < 2; ni++) {
                    MMA_BF16(acc[mi][ni], aH[mi], bH[ni]);
                    MMA_BF16(acc[mi][ni], aH[mi], bL[ni]);
                    MMA_BF16(acc[mi][ni], aL[mi], bH[ni]);
                }
        }
        __syncthreads();
    }

    const int er = lane >> 2, ec = (lane & 3) * 2;
    #pragma unroll
    for (int mi = 0; mi < 4; mi++)
        #pragma unroll
        for (int ni = 0; ni < 2; ni++) {
            size_t row = (size_t)(mb * 128 + wm + mi * 16 + er);
            size_t col = (size_t)(wn + ni * 8 + ec);
            *(float2*)(C + row * LL + col) = make_float2(acc[mi][ni][0], acc[mi][ni][1]);
            *(float2*)(C + (row + 8) * LL + col) = make_float2(acc[mi][ni][2], acc[mi][ni][3]);
        }
}

// ================= hi/lo bf16 split (x + weights) ==========================
__device__ __forceinline__ void split4(const float4 v, __nv_bfloat16* h, __nv_bfloat16* l, size_t i) {
    __nv_bfloat16 h0 = __float2bfloat16(v.x), h1 = __float2bfloat16(v.y);
    __nv_bfloat16 h2 = __float2bfloat16(v.z), h3 = __float2bfloat16(v.w);
    __nv_bfloat162* hp = (__nv_bfloat162*)(h + i);
    hp[0] = __nv_bfloat162(h0, h1); hp[1] = __nv_bfloat162(h2, h3);
    __nv_bfloat162* lp = (__nv_bfloat162*)(l + i);
    lp[0] = __nv_bfloat162(__float2bfloat16(v.x - __bfloat162float(h0)),
                           __float2bfloat16(v.y - __bfloat162float(h1)));
    lp[1] = __nv_bfloat162(__float2bfloat16(v.z - __bfloat162float(h2)),
                           __float2bfloat16(v.w - __bfloat162float(h3)));
}
__global__ void k_split_all(const float* __restrict__ x,
                            const float* __restrict__ wq, const float* __restrict__ wk,
                            const float* __restrict__ wv, const float* __restrict__ wo)
{
    int bid = blockIdx.x;
    if (bid < 2048) {
        size_t i = ((size_t)bid * 256 + threadIdx.x) * 4;
        split4(*(const float4*)(x + i), g_xh, g_xl, i);
    } else {
        int r = bid - 2048;
        int z = r >> 8;
        const float* w = (z == 0) ? wq : (z == 1 ? wk : (z == 2 ? wv : wo));
        size_t i = ((size_t)(r & 255) * 256 + threadIdx.x) * 4;
        split4(*(const float4*)(w + i), g_wh + (size_t)z * NXC * NXC,
               g_wl + (size_t)z * NXC * NXC, i);
    }
}

// ---------------- scalars ----------------
__global__ void k_scalars(const float* __restrict__ lq1, const float* __restrict__ lk1,
                          const float* __restrict__ lq2, const float* __restrict__ lk2,
                          const int* __restrict__ lp)
{
    int t = threadIdx.x;
    float v1 = lq1[t]*lk1[t];
    float v2 = lq2[t]*lk2[t];
    #pragma unroll
    for (int o=16;o;o>>=1){ v1 += __shfl_xor_sync(~0u,v1,o); v2 += __shfl_xor_sync(~0u,v2,o); }
    __shared__ float s1[4], s2[4];
    if ((t&31)==0){ s1[t>>5]=v1; s2[t>>5]=v2; }
    __syncthreads();
    if (t==0) {
        float a  = s1[0]+s1[1]+s1[2]+s1[3];
        float b2 = s2[0]+s2[1]+s2[2]+s2[3];
        float li = 0.8f - 0.6f*expf(-0.3f * (float)lp[0]);
        g_lam_init = li;
        g_lam = expf(a) - expf(b2) + li;
    }
}

// ---------------- landmark rows (heads 1..3) ------------------------------
__global__ void k_sqsk(const float* __restrict__ m1, const float* __restrict__ m2,
                       const int* __restrict__ lm)
{
    int r = blockIdx.x;               // 0..383: b*192 + hh*64 + l
    int which = blockIdx.y;
    int b = r / 192, hh = (r / 64) % 3, l = r & 63;
    int h = hh + 1, bh = b * 4 + h;
    int tl = lm[l];
    size_t idx = ((size_t)b * TT + tl) * NXC + h * HD + threadIdx.x;
    float v = which == 0
        ? __bfloat162float(g_qh[idx]) + __bfloat162float(g_ql[idx])
        : __bfloat162float(g_kh[idx]) + __bfloat162float(g_kl[idx]);
    float ss = v * v;
    #pragma unroll
    for (int o=16;o;o>>=1) ss += __shfl_xor_sync(~0u,ss,o);
    __shared__ float sh[4];
    int d = threadIdx.x;
    if ((d&31)==0) sh[d>>5] = ss;
    __syncthreads();
    float tot = sh[0]+sh[1]+sh[2]+sh[3];
    float mval = (which==0 ? m1 : m2)[h*LL + l];
    float outv = v * rsqrtf(tot) * mval;
    __nv_bfloat16 oh = __float2bfloat16(outv);
    __nv_bfloat16 ol = __float2bfloat16(outv - __bfloat162float(oh));
    size_t o2 = (size_t)bh * LL * HD + l * HD + d;
    if (which == 0) { g_sqh[o2] = oh; g_sql[o2] = ol; }
    else            { g_skh[o2] = oh; g_skl[o2] = ol; }
}

// ---------------- mask bitmap (+ vmean zero) + CSR ------------------------
__global__ void k_mask_set(const int* __restrict__ rns)
{
    int t = blockIdx.x * blockDim.x + threadIdx.x;
    if (t < BB*NXC) g_vmean[t] = 0.f;
    int b = t / (TT*KK);
    int i = (t / KK) % TT;
    int j = rns[t];
    atomicOr(&g_bits[((size_t)b*TT + i)*(TT/32) + (j>>5)], 1u << (j&31));
}
__global__ void k_mask(const int* __restrict__ rns)
{
    int gw = (blockIdx.x * blockDim.x + threadIdx.x) >> 5;
    if (gw >= BB*TT) return;
    int lane = threadIdx.x & 31;
    int b = gw / TT, i = gw % TT;
    const int* rowi = rns + ((size_t)b*TT + i)*KK;
    int j = rowi[lane];
    unsigned mm = __match_any_sync(0xffffffffu, j);
    bool first = ((mm & ((1u<<lane)-1u)) == 0u);
    bool hit = (g_bits[((size_t)b*TT + j)*(TT/32) + (i>>5)] >> (i&31)) & 1u;
    bool valid = first && hit;
    unsigned bal = __ballot_sync(0xffffffffu, valid);
    int pos = __popc(bal & ((1u<<lane)-1u));
    if (valid) g_rows[(size_t)gw*KK + pos] = j;
    if (lane==0) g_cnt[gw] = __popc(bal);
}

// ---------------- v column mean ----------------
__global__ void k_vmean()
{
    int b = blockIdx.x, seg = blockIdx.y, d = threadIdx.x;
    const float* vb = g_v + ((size_t)b*TT + seg*128)*NXC + d;
    float s = 0.f;
    #pragma unroll 4
    for (int t=0;t<128;t++) s += vb[(size_t)t*NXC];
    atomicAdd(&g_vmean[b*NXC + d], s * (1.f/(float)TT));
}

// ---------------- sparse softmax + AV + RMSNorm + bf16 split -------------
__global__ void k_sparse(const float* __restrict__ g)
{
    int row = blockIdx.x;
    int b = row >> 11, i = row & (TT-1);
    int tid = threadIdx.x;
    __shared__ int   s_j[KK];
    __shared__ float s_w1[3][LL];
    __shared__ float s_p[3][KK];
    __shared__ float s_c0[KK], s_c1[KK];
    __shared__ float s_r0[8], s_r1[8];
    int cnt = g_cnt[row];
    float lam = g_lam;
    float a0 = 0.f, a1 = 0.f;
    int d = tid;
    if (cnt == 0) {
        float c = 1.f - 2.f*lam;
        a0 = c * g_vmean[b*NXC + d];
        a1 = c * g_vmean[b*NXC + 256 + d];
    } else {
        if (tid < cnt) s_j[tid] = g_rows[(size_t)row*KK + tid];
        if (tid < 192) {
            int h = (tid >> 6) + 1, dd = tid & 63;
            s_w1[h-1][dd] = g_w1[((size_t)(b*4+h)*TT + i)*LL + dd];
        }
        __syncthreads();
        int w = tid >> 5, lane = tid & 31;
        if (w < 3) {
            float lg = -1e30f;
            if (lane < cnt) {
                const float* w2r = g_w2T + ((size_t)(b*4 + w + 1)*TT + s_j[lane])*LL;
                float s = 0.f;
                #pragma unroll
                for (int dd=0;dd<LL;dd++) s = fmaf(s_w1[w][dd], w2r[dd], s);
                lg = s;
            }
            float mx = lg;
            #pragma unroll
            for (int o=16;o;o>>=1) mx = fmaxf(mx, __shfl_xor_sync(~0u,mx,o));
            float ex = (lane < cnt) ? expf(lg - mx) : 0.f;
            float sm = ex;
            #pragma unroll
            for (int o=16;o;o>>=1) sm += __shfl_xor_sync(~0u,sm,o);
            if (lane < cnt) s_p[w][lane] = ex / sm;
        }
        __syncthreads();
        if (tid < cnt) {
            float p1 = s_p[0][tid], p2 = s_p[1][tid], p3 = s_p[2][tid];
            s_c0[tid] = -lam*p1 + (1.f-lam)*p2;
            s_c1[tid] =  p2 - p1 + (1.f-2.f*lam)*p3;
        }
        __syncthreads();
        const float* vb = g_v + (size_t)b*TT*NXC;
        for (int e=0;e<cnt;e++) {
            const float* vr = vb + (size_t)s_j[e]*NXC;
            a0 = fmaf(s_c0[e], vr[d],       a0);
            a1 = fmaf(s_c1[e], vr[256 + d], a1);
        }
    }
    float ss0 = a0*a0, ss1 = a1*a1;
    #pragma unroll
    for (int o=16;o;o>>=1){ ss0 += __shfl_xor_sync(~0u,ss0,o); ss1 += __shfl_xor_sync(~0u,ss1,o); }
    if ((tid&31)==0){ s_r0[tid>>5]=ss0; s_r1[tid>>5]=ss1; }
    __syncthreads();
    float t0=0.f, t1=0.f;
    #pragma unroll
    for (int q2=0;q2<8;q2++){ t0 += s_r0[q2]; t1 += s_r1[q2]; }
    float r0 = rsqrtf(t0*(1.f/256.f) + EPSC);
    float r1 = rsqrtf(t1*(1.f/256.f) + EPSC);
    float sc = 1.f - g_lam_init;
    float gg = g[d];
    float v0 = a0*r0*gg*sc;
    float v1 = a1*r1*gg*sc;
    size_t base = ((size_t)b*TT + i)*NXC;
    __nv_bfloat16 h0 = __float2bfloat16(v0);
    __nv_bfloat16 h1 = __float2bfloat16(v1);
    g_ah[base + d]       = h0;
    g_al[base + d]       = __float2bfloat16(v0 - __bfloat162float(h0));
    g_ah[base + 256 + d] = h1;
    g_al[base + 256 + d] = __float2bfloat16(v1 - __bfloat162float(h1));
}

// ---------------- launcher ----------------
extern "C" void kernel_launch(void* const* d_in, const int* in_sizes, int n_in,
                              void* d_out, int out_size)
{
    const float* x    = (const float*)d_in[0];
    const float* wq   = (const float*)d_in[1];
    const float* wk   = (const float*)d_in[2];
    const float* wv   = (const float*)d_in[3];
    const float* wo   = (const float*)d_in[4];
    const float* m1   = (const float*)d_in[5];
    const float* m2   = (const float*)d_in[6];
    const float* lq1  = (const float*)d_in[7];
    const float* lk1  = (const float*)d_in[8];
    const float* lq2  = (const float*)d_in[9];
    const float* lk2  = (const float*)d_in[10];
    const float* rmsg = (const float*)d_in[11];
    const int*   lp   = (const int*)d_in[12];
    const int*   rns  = (const int*)d_in[14];
    const int*   lm   = (const int*)d_in[15];
    float* out = (float*)d_out;

    static int smem_set = 0;
    if (!smem_set) {
        cudaFuncSetAttribute(k_mma, cudaFuncAttributeMaxDynamicSharedMemorySize, SMEMB);
        cudaFuncSetAttribute(k_w12m, cudaFuncAttributeMaxDynamicSharedMemorySize, W_SMEM);
        smem_set = 1;
    }

    k_scalars<<<1, 128>>>(lq1, lk1, lq2, lk2, lp);
    k_split_all<<<3072, 256>>>(x, wq, wk, wv, wo);
    k_mask_set<<<BB*TT*KK/256, 256>>>(rns);
    k_mma<<<148, 256, SMEMB>>>(0, nullptr);
    k_sqsk<<<dim3(384, 2), 128>>>(m1, m2, lm);
    k_mask<<<(BB*TT)/8, 256>>>(rns);
    k_vmean<<<dim3(BB, TT/128), NXC>>>();
    k_w12m<<<192, 256, W_SMEM>>>();
    k_sparse<<<BB*TT, 256>>>(rmsg);
    k_mma<<<148, 256, SMEMB>>>(1, out);
}

// round 10
// speedup vs baseline: 1.6170x; 1.6170x over previous
#include <cuda_runtime.h>
#include <cuda_bf16.h>
#include <math.h>
#include <stdint.h>

#define BB   2
#define TT   2048
#define NXC  512
#define HD   128
#define LL   64
#define KK   32
#define EPSC 1e-5f

// ---------------- device scratch ----------------
__device__ float g_v[BB*TT*NXC];
__device__ float g_w1 [BB*4*TT*LL];
__device__ float g_w2T[BB*4*TT*LL];
__device__ float g_vmean[BB*NXC];
__device__ int   g_cnt [BB*TT];
__device__ int   g_rows[BB*TT*KK];
__device__ float g_lam, g_lam_init;
__device__ __nv_bfloat16 g_xh[BB*TT*NXC];
__device__ __nv_bfloat16 g_xl[BB*TT*NXC];
__device__ __nv_bfloat16 g_wh[4*NXC*NXC];
__device__ __nv_bfloat16 g_wl[4*NXC*NXC];
__device__ __nv_bfloat16 g_ah[BB*TT*NXC];
__device__ __nv_bfloat16 g_al[BB*TT*NXC];
__device__ __nv_bfloat16 g_qh[BB*TT*NXC];
__device__ __nv_bfloat16 g_ql[BB*TT*NXC];
__device__ __nv_bfloat16 g_kh[BB*TT*NXC];
__device__ __nv_bfloat16 g_kl[BB*TT*NXC];
__device__ __nv_bfloat16 g_sqh[8*LL*HD], g_sql[8*LL*HD];
__device__ __nv_bfloat16 g_skh[8*LL*HD], g_skl[8*LL*HD];
__device__ unsigned g_bits[BB*TT*(TT/32)];

__device__ __forceinline__ uint32_t smem_u32(const void* p) {
    uint32_t a;
    asm("{ .reg .u64 t; cvta.to.shared.u64 t, %1; cvt.u32.u64 %0, t; }" : "=r"(a) : "l"(p));
    return a;
}
#define CP16(dst, src) \
    asm volatile("cp.async.cg.shared.global [%0], [%1], 16;" :: "r"(dst), "l"(src))
#define MMA_BF16(acc, a, b) \
    asm volatile("mma.sync.aligned.m16n8k16.row.col.f32.bf16.bf16.f32 " \
        "{%0,%1,%2,%3}, {%4,%5,%6,%7}, {%8,%9}, {%0,%1,%2,%3};" \
        : "+f"((acc)[0]), "+f"((acc)[1]), "+f"((acc)[2]), "+f"((acc)[3]) \
        : "r"((a)[0]), "r"((a)[1]), "r"((a)[2]), "r"((a)[3]), "r"((b)[0]), "r"((b)[1]))

// ============ HMMA split-bf16 GEMM, cp.async double-buffered, persistent ===
#define SST  40
#define MATB (128*SST*2)
#define BUFB (4*MATB)
#define SMEMB (2*BUFB)
__global__ void __launch_bounds__(256, 2) k_mma(int mode, float* __restrict__ outp)
{
    extern __shared__ __align__(16) char dsm[];
    const int tid = threadIdx.x, lane = tid & 31, wid = tid >> 5;
    const uint32_t sbase = smem_u32(dsm);
    const int ntiles = (mode == 0) ? 320 : 128;

    const int lr = tid >> 2, lq = tid & 3;
    const uint32_t so  = (uint32_t)(lr * SST + lq * 8) * 2;
    const uint32_t so2 = so + 64 * SST * 2;

    const int wm = (wid >> 2) * 64;
    const int wn = (wid & 3) * 32;
    uint32_t aoff[4], boff[4];
    {
        int arow = wm + (lane & 15);
        int acol = ((lane >> 4) & 1) * 8;
        #pragma unroll
        for (int mi = 0; mi < 4; mi++)
            aoff[mi] = (uint32_t)((arow + mi * 16) * SST + acol) * 2;
        int l15 = lane & 15;
        int brow = wn + (l15 & 7);
        int bcol = ((l15 >> 3) & 1) * 8;
        #pragma unroll
        for (int ni = 0; ni < 4; ni++)
            boff[ni] = (uint32_t)((brow + ni * 8) * SST + bcol) * 2;
    }

    const __nv_bfloat16* Abase_h = (mode == 0) ? g_xh : g_ah;
    const __nv_bfloat16* Abase_l = (mode == 0) ? g_xl : g_al;

    for (int t = blockIdx.x; t < ntiles; t += gridDim.x) {
        int z, mb, nb;
        if (mode == 0) {
            if (t < 192) { z = t / 96; int r = t % 96; nb = r % 3 + 1; mb = r / 3; }
            else         { z = 2; int r = t - 192; nb = r & 3; mb = r >> 2; }
        } else { z = 3; nb = t & 3; mb = t >> 2; }
        const int m0 = mb * 128, n0 = nb * 128;
        const __nv_bfloat16* Bh = g_wh + (size_t)z * NXC * NXC;
        const __nv_bfloat16* Bl = g_wl + (size_t)z * NXC * NXC;

        const size_t gA0 = (size_t)(m0 + lr) * NXC + lq * 8;
        const size_t gA1 = gA0 + (size_t)64 * NXC;
        const size_t gB0 = (size_t)(n0 + lr) * NXC + lq * 8;
        const size_t gB1 = gB0 + (size_t)64 * NXC;

        auto issue = [&](int ch, int p) {
            uint32_t s0 = sbase + (uint32_t)p * BUFB;
            int ko = ch * 32;
            CP16(s0 + so,           Abase_h + gA0 + ko);
            CP16(s0 + so2,          Abase_h + gA1 + ko);
            CP16(s0 + MATB + so,    Abase_l + gA0 + ko);
            CP16(s0 + MATB + so2,   Abase_l + gA1 + ko);
            CP16(s0 + 2*MATB + so,  Bh + gB0 + ko);
            CP16(s0 + 2*MATB + so2, Bh + gB1 + ko);
            CP16(s0 + 3*MATB + so,  Bl + gB0 + ko);
            CP16(s0 + 3*MATB + so2, Bl + gB1 + ko);
            asm volatile("cp.async.commit_group;" ::: "memory");
        };

        float acc[4][4][4];
        #pragma unroll
        for (int a = 0; a < 4; a++)
            #pragma unroll
            for (int b = 0; b < 4; b++)
                #pragma unroll
                for (int c = 0; c < 4; c++) acc[a][b][c] = 0.f;

        issue(0, 0);
        for (int ch = 0; ch < 16; ch++) {
            if (ch + 1 < 16) {
                issue(ch + 1, (ch + 1) & 1);
                asm volatile("cp.async.wait_group 1;" ::: "memory");
            } else {
                asm volatile("cp.async.wait_group 0;" ::: "memory");
            }
            __syncthreads();

            uint32_t mb_ = sbase + (uint32_t)(ch & 1) * BUFB;
            #pragma unroll
            for (int kk = 0; kk < 2; kk++) {
                uint32_t koff = (uint32_t)kk * 32;
                uint32_t aH[4][4], aL[4][4], bH[4][2], bL[4][2];
                #pragma unroll
                for (int mi = 0; mi < 4; mi++)
                    asm volatile("ldmatrix.sync.aligned.m8n8.x4.shared.b16 {%0,%1,%2,%3}, [%4];"
                        : "=r"(aH[mi][0]), "=r"(aH[mi][1]), "=r"(aH[mi][2]), "=r"(aH[mi][3])
                        : "r"(mb_ + aoff[mi] + koff));
                #pragma unroll
                for (int mi = 0; mi < 4; mi++)
                    asm volatile("ldmatrix.sync.aligned.m8n8.x4.shared.b16 {%0,%1,%2,%3}, [%4];"
                        : "=r"(aL[mi][0]), "=r"(aL[mi][1]), "=r"(aL[mi][2]), "=r"(aL[mi][3])
                        : "r"(mb_ + MATB + aoff[mi] + koff));
                #pragma unroll
                for (int ni = 0; ni < 4; ni++)
                    asm volatile("ldmatrix.sync.aligned.m8n8.x2.shared.b16 {%0,%1}, [%2];"
                        : "=r"(bH[ni][0]), "=r"(bH[ni][1])
                        : "r"(mb_ + 2*MATB + boff[ni] + koff));
                #pragma unroll
                for (int ni = 0; ni < 4; ni++)
                    asm volatile("ldmatrix.sync.aligned.m8n8.x2.shared.b16 {%0,%1}, [%2];"
                        : "=r"(bL[ni][0]), "=r"(bL[ni][1])
                        : "r"(mb_ + 3*MATB + boff[ni] + koff));
                #pragma unroll
                for (int mi = 0; mi < 4; mi++)
                    #pragma unroll
                    for (int ni = 0; ni < 4; ni++) {
                        MMA_BF16(acc[mi][ni], aH[mi], bH[ni]);
                        MMA_BF16(acc[mi][ni], aH[mi], bL[ni]);
                        MMA_BF16(acc[mi][ni], aL[mi], bH[ni]);
                    }
            }
            __syncthreads();
        }

        const int er = lane >> 2, ec = (lane & 3) * 2;
        if (mode == 0 && z < 2) {
            __nv_bfloat16* H = z ? g_kh : g_qh;
            __nv_bfloat16* L = z ? g_kl : g_ql;
            #pragma unroll
            for (int mi = 0; mi < 4; mi++)
                #pragma unroll
                for (int ni = 0; ni < 4; ni++)
                    #pragma unroll
                    for (int half = 0; half < 2; half++) {
                        size_t row = (size_t)(m0 + wm + mi * 16 + er + half * 8);
                        size_t col = (size_t)(n0 + wn + ni * 8 + ec);
                        float v0 = acc[mi][ni][half*2], v1 = acc[mi][ni][half*2+1];
                        __nv_bfloat16 h0 = __float2bfloat16(v0);
                        __nv_bfloat16 h1 = __float2bfloat16(v1);
                        *(__nv_bfloat162*)(H + row * NXC + col) = __nv_bfloat162(h0, h1);
                        *(__nv_bfloat162*)(L + row * NXC + col) = __nv_bfloat162(
                            __float2bfloat16(v0 - __bfloat162float(h0)),
                            __float2bfloat16(v1 - __bfloat162float(h1)));
                    }
        } else {
            float* C = (mode == 0) ? g_v : outp;
            #pragma unroll
            for (int mi = 0; mi < 4; mi++)
                #pragma unroll
                for (int ni = 0; ni < 4; ni++) {
                    size_t row = (size_t)(m0 + wm + mi * 16 + er);
                    size_t col = (size_t)(n0 + wn + ni * 8 + ec);
                    *(float2*)(C + row * NXC + col) =
                        make_float2(acc[mi][ni][0], acc[mi][ni][1]);
                    *(float2*)(C + (row + 8) * NXC + col) =
                        make_float2(acc[mi][ni][2], acc[mi][ni][3]);
                }
        }
    }
}

// ============ HMMA w1/w2T: 12 gemms M=2048 N=64 K=128, heads 1..3 =========
#define W_AB (128*SST*2)
#define W_BB (64*SST*2)
#define W_STG (2*W_AB + 2*W_BB)
#define W_SMEM (2*W_STG)
__global__ void __launch_bounds__(256, 2) k_w12m()
{
    extern __shared__ __align__(16) char dsm[];
    const int tid = threadIdx.x, lane = tid & 31, wid = tid >> 5;
    const uint32_t sbase = smem_u32(dsm);

    int t = blockIdx.x;
    int g = t >> 4, mb = t & 15;
    int isw2 = (g >= 6);
    if (isw2) g -= 6;
    int b = g / 3, h = g % 3 + 1, bh = b * 4 + h;
    const __nv_bfloat16* AH = isw2 ? g_kh : g_qh;
    const __nv_bfloat16* AL = isw2 ? g_kl : g_ql;
    const __nv_bfloat16* BH = (isw2 ? g_sqh : g_skh) + (size_t)bh * LL * HD;
    const __nv_bfloat16* BL = (isw2 ? g_sql : g_skl) + (size_t)bh * LL * HD;
    float* C = (isw2 ? g_w2T : g_w1) + (size_t)bh * TT * LL;

    const int lr = tid >> 2, lq = tid & 3;
    const uint32_t soA  = (uint32_t)(lr * SST + lq * 8) * 2;
    const uint32_t soA2 = soA + 64 * SST * 2;
    const size_t gA0 = (size_t)(b * TT + mb * 128 + lr) * NXC + h * HD + lq * 8;
    const size_t gA1 = gA0 + (size_t)64 * NXC;
    const size_t gB  = (size_t)lr * HD + lq * 8;

    const int wm = (wid >> 2) * 64;
    const int wn = (wid & 3) * 16;
    uint32_t aoff[4], boff[2];
    {
        int arow = wm + (lane & 15);
        int acol = ((lane >> 4) & 1) * 8;
        #pragma unroll
        for (int mi = 0; mi < 4; mi++)
            aoff[mi] = (uint32_t)((arow + mi * 16) * SST + acol) * 2;
        int l15 = lane & 15;
        int brow = wn + (l15 & 7);
        int bcol = ((l15 >> 3) & 1) * 8;
        #pragma unroll
        for (int ni = 0; ni < 2; ni++)
            boff[ni] = (uint32_t)((brow + ni * 8) * SST + bcol) * 2;
    }

    auto issue = [&](int ch, int p) {
        uint32_t s0 = sbase + (uint32_t)p * W_STG;
        int ko = ch * 32;
        CP16(s0 + soA,                 AH + gA0 + ko);
        CP16(s0 + soA2,                AH + gA1 + ko);
        CP16(s0 + W_AB + soA,          AL + gA0 + ko);
        CP16(s0 + W_AB + soA2,         AL + gA1 + ko);
        CP16(s0 + 2*W_AB + soA,        BH + gB + ko);
        CP16(s0 + 2*W_AB + W_BB + soA, BL + gB + ko);
        asm volatile("cp.async.commit_group;" ::: "memory");
    };

    float acc[4][2][4];
    #pragma unroll
    for (int a = 0; a < 4; a++)
        #pragma unroll
        for (int b2 = 0; b2 < 2; b2++)
            #pragma unroll
            for (int c = 0; c < 4; c++) acc[a][b2][c] = 0.f;

    issue(0, 0);
    for (int ch = 0; ch < 4; ch++) {
        if (ch + 1 < 4) {
            issue(ch + 1, (ch + 1) & 1);
            asm volatile("cp.async.wait_group 1;" ::: "memory");
        } else {
            asm volatile("cp.async.wait_group 0;" ::: "memory");
        }
        __syncthreads();

        uint32_t mb_ = sbase + (uint32_t)(ch & 1) * W_STG;
        #pragma unroll
        for (int kk = 0; kk < 2; kk++) {
            uint32_t koff = (uint32_t)kk * 32;
            uint32_t aH[4][4], aL[4][4], bH[2][2], bL[2][2];
            #pragma unroll
            for (int mi = 0; mi < 4; mi++)
                asm volatile("ldmatrix.sync.aligned.m8n8.x4.shared.b16 {%0,%1,%2,%3}, [%4];"
                    : "=r"(aH[mi][0]), "=r"(aH[mi][1]), "=r"(aH[mi][2]), "=r"(aH[mi][3])
                    : "r"(mb_ + aoff[mi] + koff));
            #pragma unroll
            for (int mi = 0; mi < 4; mi++)
                asm volatile("ldmatrix.sync.aligned.m8n8.x4.shared.b16 {%0,%1,%2,%3}, [%4];"
                    : "=r"(aL[mi][0]), "=r"(aL[mi][1]), "=r"(aL[mi][2]), "=r"(aL[mi][3])
                    : "r"(mb_ + W_AB + aoff[mi] + koff));
            #pragma unroll
            for (int ni = 0; ni < 2; ni++)
                asm volatile("ldmatrix.sync.aligned.m8n8.x2.shared.b16 {%0,%1}, [%2];"
                    : "=r"(bH[ni][0]), "=r"(bH[ni][1])
                    : "r"(mb_ + 2*W_AB + boff[ni] + koff));
            #pragma unroll
            for (int ni = 0; ni < 2; ni++)
                asm volatile("ldmatrix.sync.aligned.m8n8.x2.shared.b16 {%0,%1}, [%2];"
                    : "=r"(bL[ni][0]), "=r"(bL[ni][1])
                    : "r"(mb_ + 2*W_AB + W_BB + boff[ni] + koff));
            #pragma unroll
            for (int mi = 0; mi < 4; mi++)
                #pragma unroll
                for (int ni = 0; ni < 2; ni++) {
                    MMA_BF16(acc[mi][ni], aH[mi], bH[ni]);
                    MMA_BF16(acc[mi][ni], aH[mi], bL[ni]);
                    MMA_BF16(acc[mi][ni], aL[mi], bH[ni]);
                }
        }
        __syncthreads();
    }

    const int er = lane >> 2, ec = (lane & 3) * 2;
    #pragma unroll
    for (int mi = 0; mi < 4; mi++)
        #pragma unroll
        for (int ni = 0; ni < 2; ni++) {
            size_t row = (size_t)(mb * 128 + wm + mi * 16 + er);
            size_t col = (size_t)(wn + ni * 8 + ec);
            *(float2*)(C + row * LL + col) = make_float2(acc[mi][ni][0], acc[mi][ni][1]);
            *(float2*)(C + (row + 8) * LL + col) = make_float2(acc[mi][ni][2], acc[mi][ni][3]);
        }
}

// ================= hi/lo bf16 split (x + weights) ==========================
__device__ __forceinline__ void split4(const float4 v, __nv_bfloat16* h, __nv_bfloat16* l, size_t i) {
    __nv_bfloat16 h0 = __float2bfloat16(v.x), h1 = __float2bfloat16(v.y);
    __nv_bfloat16 h2 = __float2bfloat16(v.z), h3 = __float2bfloat16(v.w);
    __nv_bfloat162* hp = (__nv_bfloat162*)(h + i);
    hp[0] = __nv_bfloat162(h0, h1); hp[1] = __nv_bfloat162(h2, h3);
    __nv_bfloat162* lp = (__nv_bfloat162*)(l + i);
    lp[0] = __nv_bfloat162(__float2bfloat16(v.x - __bfloat162float(h0)),
                           __float2bfloat16(v.y - __bfloat162float(h1)));
    lp[1] = __nv_bfloat162(__float2bfloat16(v.z - __bfloat162float(h2)),
                           __float2bfloat16(v.w - __bfloat162float(h3)));
}
__global__ void k_split_all(const float* __restrict__ x,
                            const float* __restrict__ wq, const float* __restrict__ wk,
                            const float* __restrict__ wv, const float* __restrict__ wo)
{
    int bid = blockIdx.x;
    if (bid < 2048) {
        size_t i = ((size_t)bid * 256 + threadIdx.x) * 4;
        split4(*(const float4*)(x + i), g_xh, g_xl, i);
    } else {
        int r = bid - 2048;
        int z = r >> 8;
        const float* w = (z == 0) ? wq : (z == 1 ? wk : (z == 2 ? wv : wo));
        size_t i = ((size_t)(r & 255) * 256 + threadIdx.x) * 4;
        split4(*(const float4*)(w + i), g_wh + (size_t)z * NXC * NXC,
               g_wl + (size_t)z * NXC * NXC, i);
    }
}

// ---------------- scalars ----------------
__global__ void k_scalars(const float* __restrict__ lq1, const float* __restrict__ lk1,
                          const float* __restrict__ lq2, const float* __restrict__ lk2,
                          const int* __restrict__ lp)
{
    int t = threadIdx.x;
    float v1 = lq1[t]*lk1[t];
    float v2 = lq2[t]*lk2[t];
    #pragma unroll
    for (int o=16;o;o>>=1){ v1 += __shfl_xor_sync(~0u,v1,o); v2 += __shfl_xor_sync(~0u,v2,o); }
    __shared__ float s1[4], s2[4];
    if ((t&31)==0){ s1[t>>5]=v1; s2[t>>5]=v2; }
    __syncthreads();
    if (t==0) {
        float a  = s1[0]+s1[1]+s1[2]+s1[3];
        float b2 = s2[0]+s2[1]+s2[2]+s2[3];
        float li = 0.8f - 0.6f*expf(-0.3f * (float)lp[0]);
        g_lam_init = li;
        g_lam = expf(a) - expf(b2) + li;
    }
}

// ---------------- landmark rows (heads 1..3) ------------------------------
__global__ void k_sqsk(const float* __restrict__ m1, const float* __restrict__ m2,
                       const int* __restrict__ lm)
{
    int r = blockIdx.x;
    int which = blockIdx.y;
    int b = r / 192, hh = (r / 64) % 3, l = r & 63;
    int h = hh + 1, bh = b * 4 + h;
    int tl = lm[l];
    size_t idx = ((size_t)b * TT + tl) * NXC + h * HD + threadIdx.x;
    float v = which == 0
        ? __bfloat162float(g_qh[idx]) + __bfloat162float(g_ql[idx])
        : __bfloat162float(g_kh[idx]) + __bfloat162float(g_kl[idx]);
    float ss = v * v;
    #pragma unroll
    for (int o=16;o;o>>=1) ss += __shfl_xor_sync(~0u,ss,o);
    __shared__ float sh[4];
    int d = threadIdx.x;
    if ((d&31)==0) sh[d>>5] = ss;
    __syncthreads();
    float tot = sh[0]+sh[1]+sh[2]+sh[3];
    float mval = (which==0 ? m1 : m2)[h*LL + l];
    float outv = v * rsqrtf(tot) * mval;
    __nv_bfloat16 oh = __float2bfloat16(outv);
    __nv_bfloat16 ol = __float2bfloat16(outv - __bfloat162float(oh));
    size_t o2 = (size_t)bh * LL * HD + l * HD + d;
    if (which == 0) { g_sqh[o2] = oh; g_sql[o2] = ol; }
    else            { g_skh[o2] = oh; g_skl[o2] = ol; }
}

// ---------------- mask bitmap (+ vmean zero) + CSR ------------------------
__global__ void k_mask_set(const int* __restrict__ rns)
{
    int t = blockIdx.x * blockDim.x + threadIdx.x;
    if (t < BB*NXC) g_vmean[t] = 0.f;
    int b = t / (TT*KK);
    int i = (t / KK) % TT;
    int j = rns[t];
    atomicOr(&g_bits[((size_t)b*TT + i)*(TT/32) + (j>>5)], 1u << (j&31));
}
__global__ void k_mask(const int* __restrict__ rns)
{
    int gw = (blockIdx.x * blockDim.x + threadIdx.x) >> 5;
    if (gw >= BB*TT) return;
    int lane = threadIdx.x & 31;
    int b = gw / TT, i = gw % TT;
    const int* rowi = rns + ((size_t)b*TT + i)*KK;
    int j = rowi[lane];
    unsigned mm = __match_any_sync(0xffffffffu, j);
    bool first = ((mm & ((1u<<lane)-1u)) == 0u);
    bool hit = (g_bits[((size_t)b*TT + j)*(TT/32) + (i>>5)] >> (i&31)) & 1u;
    bool valid = first && hit;
    unsigned bal = __ballot_sync(0xffffffffu, valid);
    int pos = __popc(bal & ((1u<<lane)-1u));
    if (valid) g_rows[(size_t)gw*KK + pos] = j;
    if (lane==0) g_cnt[gw] = __popc(bal);
}

// ---------------- v column mean ----------------
__global__ void k_vmean()
{
    int b = blockIdx.x, seg = blockIdx.y, d = threadIdx.x;
    const float* vb = g_v + ((size_t)b*TT + seg*128)*NXC + d;
    float s = 0.f;
    #pragma unroll 4
    for (int t=0;t<128;t++) s += vb[(size_t)t*NXC];
    atomicAdd(&g_vmean[b*NXC + d], s * (1.f/(float)TT));
}

// ---------------- sparse softmax + AV + RMSNorm + bf16 split -------------
__global__ void k_sparse(const float* __restrict__ g)
{
    int row = blockIdx.x;
    int b = row >> 11, i = row & (TT-1);
    int tid = threadIdx.x;
    __shared__ int   s_j[KK];
    __shared__ float s_w1[3][LL];
    __shared__ float s_p[3][KK];
    __shared__ float s_c0[KK], s_c1[KK];
    __shared__ float s_r0[8], s_r1[8];
    int cnt = g_cnt[row];
    float lam = g_lam;
    float a0 = 0.f, a1 = 0.f;
    int d = tid;
    if (cnt == 0) {
        float c = 1.f - 2.f*lam;
        a0 = c * g_vmean[b*NXC + d];
        a1 = c * g_vmean[b*NXC + 256 + d];
    } else {
        if (tid < cnt) s_j[tid] = g_rows[(size_t)row*KK + tid];
        if (tid < 192) {
            int h = (tid >> 6) + 1, dd = tid & 63;
            s_w1[h-1][dd] = g_w1[((size_t)(b*4+h)*TT + i)*LL + dd];
        }
        __syncthreads();
        int w = tid >> 5, lane = tid & 31;
        if (w < 3) {
            float lg = -1e30f;
            if (lane < cnt) {
                const float* w2r = g_w2T + ((size_t)(b*4 + w + 1)*TT + s_j[lane])*LL;
                float s = 0.f;
                #pragma unroll
                for (int dd=0;dd<LL;dd++) s = fmaf(s_w1[w][dd], w2r[dd], s);
                lg = s;
            }
            float mx = lg;
            #pragma unroll
            for (int o=16;o;o>>=1) mx = fmaxf(mx, __shfl_xor_sync(~0u,mx,o));
            float ex = (lane < cnt) ? expf(lg - mx) : 0.f;
            float sm = ex;
            #pragma unroll
            for (int o=16;o;o>>=1) sm += __shfl_xor_sync(~0u,sm,o);
            if (lane < cnt) s_p[w][lane] = ex / sm;
        }
        __syncthreads();
        if (tid < cnt) {
            float p1 = s_p[0][tid], p2 = s_p[1][tid], p3 = s_p[2][tid];
            s_c0[tid] = -lam*p1 + (1.f-lam)*p2;
            s_c1[tid] =  p2 - p1 + (1.f-2.f*lam)*p3;
        }
        __syncthreads();
        const float* vb = g_v + (size_t)b*TT*NXC;
        for (int e=0;e<cnt;e++) {
            const float* vr = vb + (size_t)s_j[e]*NXC;
            a0 = fmaf(s_c0[e], vr[d],       a0);
            a1 = fmaf(s_c1[e], vr[256 + d], a1);
        }
    }
    float ss0 = a0*a0, ss1 = a1*a1;
    #pragma unroll
    for (int o=16;o;o>>=1){ ss0 += __shfl_xor_sync(~0u,ss0,o); ss1 += __shfl_xor_sync(~0u,ss1,o); }
    if ((tid&31)==0){ s_r0[tid>>5]=ss0; s_r1[tid>>5]=ss1; }
    __syncthreads();
    float t0=0.f, t1=0.f;
    #pragma unroll
    for (int q2=0;q2<8;q2++){ t0 += s_r0[q2]; t1 += s_r1[q2]; }
    float r0 = rsqrtf(t0*(1.f/256.f) + EPSC);
    float r1 = rsqrtf(t1*(1.f/256.f) + EPSC);
    float sc = 1.f - g_lam_init;
    float gg = g[d];
    float v0 = a0*r0*gg*sc;
    float v1 = a1*r1*gg*sc;
    size_t base = ((size_t)b*TT + i)*NXC;
    __nv_bfloat16 h0 = __float2bfloat16(v0);
    __nv_bfloat16 h1 = __float2bfloat16(v1);
    g_ah[base + d]       = h0;
    g_al[base + d]       = __float2bfloat16(v0 - __bfloat162float(h0));
    g_ah[base + 256 + d] = h1;
    g_al[base + 256 + d] = __float2bfloat16(v1 - __bfloat162float(h1));
}

// ---------------- launcher ----------------
extern "C" void kernel_launch(void* const* d_in, const int* in_sizes, int n_in,
                              void* d_out, int out_size)
{
    const float* x    = (const float*)d_in[0];
    const float* wq   = (const float*)d_in[1];
    const float* wk   = (const float*)d_in[2];
    const float* wv   = (const float*)d_in[3];
    const float* wo   = (const float*)d_in[4];
    const float* m1   = (const float*)d_in[5];
    const float* m2   = (const float*)d_in[6];
    const float* lq1  = (const float*)d_in[7];
    const float* lk1  = (const float*)d_in[8];
    const float* lq2  = (const float*)d_in[9];
    const float* lk2  = (const float*)d_in[10];
    const float* rmsg = (const float*)d_in[11];
    const int*   lp   = (const int*)d_in[12];
    const int*   rns  = (const int*)d_in[14];
    const int*   lm   = (const int*)d_in[15];
    float* out = (float*)d_out;

    static int smem_set = 0;
    if (!smem_set) {
        cudaFuncSetAttribute(k_mma, cudaFuncAttributeMaxDynamicSharedMemorySize, SMEMB);
        cudaFuncSetAttribute(k_w12m, cudaFuncAttributeMaxDynamicSharedMemorySize, W_SMEM);
        smem_set = 1;
    }

    k_scalars<<<1, 128>>>(lq1, lk1, lq2, lk2, lp);
    k_split_all<<<3072, 256>>>(x, wq, wk, wv, wo);
    k_mask_set<<<BB*TT*KK/256, 256>>>(rns);
    k_mma<<<296, 256, SMEMB>>>(0, nullptr);
    k_sqsk<<<dim3(384, 2), 128>>>(m1, m2, lm);
    k_mask<<<(BB*TT)/8, 256>>>(rns);
    k_vmean<<<dim3(BB, TT/128), NXC>>>();
    k_w12m<<<192, 256, W_SMEM>>>();
    k_sparse<<<BB*TT, 256>>>(rmsg);
    k_mma<<<128, 256, SMEMB>>>(1, out);
}

// round 12
// speedup vs baseline: 1.7509x; 1.0828x over previous
#include <cuda_runtime.h>
#include <cuda_bf16.h>
#include <math.h>
#include <stdint.h>

#define BB   2
#define TT   2048
#define NXC  512
#define HD   128
#define LL   64
#define KK   32
#define EPSC 1e-5f

// ---------------- device scratch ----------------
__device__ float g_v[BB*TT*NXC];
__device__ float g_w1 [BB*4*TT*LL];
__device__ float g_w2T[BB*4*TT*LL];
__device__ float g_vmean[BB*NXC];
__device__ int   g_cnt [BB*TT];
__device__ int   g_rows[BB*TT*KK];
__device__ float g_lam, g_lam_init;
__device__ __nv_bfloat16 g_xh[BB*TT*NXC];
__device__ __nv_bfloat16 g_xl[BB*TT*NXC];
__device__ __nv_bfloat16 g_wh[4*NXC*NXC];
__device__ __nv_bfloat16 g_wl[4*NXC*NXC];
__device__ __nv_bfloat16 g_ah[BB*TT*NXC];
__device__ __nv_bfloat16 g_al[BB*TT*NXC];
__device__ __nv_bfloat16 g_qh[BB*TT*NXC];
__device__ __nv_bfloat16 g_ql[BB*TT*NXC];
__device__ __nv_bfloat16 g_kh[BB*TT*NXC];
__device__ __nv_bfloat16 g_kl[BB*TT*NXC];
__device__ __nv_bfloat16 g_sqh[8*LL*HD], g_sql[8*LL*HD];
__device__ __nv_bfloat16 g_skh[8*LL*HD], g_skl[8*LL*HD];
__device__ unsigned g_bits[BB*TT*(TT/32)];

__device__ __forceinline__ uint32_t smem_u32(const void* p) {
    uint32_t a;
    asm("{ .reg .u64 t; cvta.to.shared.u64 t, %1; cvt.u32.u64 %0, t; }" : "=r"(a) : "l"(p));
    return a;
}
#define CP16(dst, src) \
    asm volatile("cp.async.cg.shared.global [%0], [%1], 16;" :: "r"(dst), "l"(src))
#define MMA_BF16(acc, a, b) \
    asm volatile("mma.sync.aligned.m16n8k16.row.col.f32.bf16.bf16.f32 " \
        "{%0,%1,%2,%3}, {%4,%5,%6,%7}, {%8,%9}, {%0,%1,%2,%3};" \
        : "+f"((acc)[0]), "+f"((acc)[1]), "+f"((acc)[2]), "+f"((acc)[3]) \
        : "r"((a)[0]), "r"((a)[1]), "r"((a)[2]), "r"((a)[3]), "r"((b)[0]), "r"((b)[1]))

// ============ HMMA split-bf16 GEMM, cp.async double-buffered ==============
// mode 0: qk projection (192 tiles, z in {0,1}, nb in {1,2,3})
// mode 2: v projection  (128 tiles, z=2)
#define SST  40
#define MATB (128*SST*2)
#define BUFB (4*MATB)
#define SMEMB (2*BUFB)
__global__ void __launch_bounds__(256, 2) k_mma(int mode, float* __restrict__ outp)
{
    extern __shared__ __align__(16) char dsm[];
    const int tid = threadIdx.x, lane = tid & 31, wid = tid >> 5;
    const uint32_t sbase = smem_u32(dsm);

    const int lr = tid >> 2, lq = tid & 3;
    const uint32_t so  = (uint32_t)(lr * SST + lq * 8) * 2;
    const uint32_t so2 = so + 64 * SST * 2;

    const int wm = (wid >> 2) * 64;
    const int wn = (wid & 3) * 32;
    uint32_t aoff[4], boff[4];
    {
        int arow = wm + (lane & 15);
        int acol = ((lane >> 4) & 1) * 8;
        #pragma unroll
        for (int mi = 0; mi < 4; mi++)
            aoff[mi] = (uint32_t)((arow + mi * 16) * SST + acol) * 2;
        int l15 = lane & 15;
        int brow = wn + (l15 & 7);
        int bcol = ((l15 >> 3) & 1) * 8;
        #pragma unroll
        for (int ni = 0; ni < 4; ni++)
            boff[ni] = (uint32_t)((brow + ni * 8) * SST + bcol) * 2;
    }

    int t = blockIdx.x;
    int z, mb, nb;
    if (mode == 0) { z = t / 96; int r = t % 96; nb = r % 3 + 1; mb = r / 3; }
    else           { z = 2; nb = t & 3; mb = t >> 2; }
    const int m0 = mb * 128, n0 = nb * 128;
    const __nv_bfloat16* Bh = g_wh + (size_t)z * NXC * NXC;
    const __nv_bfloat16* Bl = g_wl + (size_t)z * NXC * NXC;

    const size_t gA0 = (size_t)(m0 + lr) * NXC + lq * 8;
    const size_t gA1 = gA0 + (size_t)64 * NXC;
    const size_t gB0 = (size_t)(n0 + lr) * NXC + lq * 8;
    const size_t gB1 = gB0 + (size_t)64 * NXC;

    auto issue = [&](int ch, int p) {
        uint32_t s0 = sbase + (uint32_t)p * BUFB;
        int ko = ch * 32;
        CP16(s0 + so,           g_xh + gA0 + ko);
        CP16(s0 + so2,          g_xh + gA1 + ko);
        CP16(s0 + MATB + so,    g_xl + gA0 + ko);
        CP16(s0 + MATB + so2,   g_xl + gA1 + ko);
        CP16(s0 + 2*MATB + so,  Bh + gB0 + ko);
        CP16(s0 + 2*MATB + so2, Bh + gB1 + ko);
        CP16(s0 + 3*MATB + so,  Bl + gB0 + ko);
        CP16(s0 + 3*MATB + so2, Bl + gB1 + ko);
        asm volatile("cp.async.commit_group;" ::: "memory");
    };

    float acc[4][4][4];
    #pragma unroll
    for (int a = 0; a < 4; a++)
        #pragma unroll
        for (int b = 0; b < 4; b++)
            #pragma unroll
            for (int c = 0; c < 4; c++) acc[a][b][c] = 0.f;

    issue(0, 0);
    for (int ch = 0; ch < 16; ch++) {
        if (ch + 1 < 16) {
            issue(ch + 1, (ch + 1) & 1);
            asm volatile("cp.async.wait_group 1;" ::: "memory");
        } else {
            asm volatile("cp.async.wait_group 0;" ::: "memory");
        }
        __syncthreads();

        uint32_t mb_ = sbase + (uint32_t)(ch & 1) * BUFB;
        #pragma unroll
        for (int kk = 0; kk < 2; kk++) {
            uint32_t koff = (uint32_t)kk * 32;
            uint32_t aH[4][4], aL[4][4], bH[4][2], bL[4][2];
            #pragma unroll
            for (int mi = 0; mi < 4; mi++)
                asm volatile("ldmatrix.sync.aligned.m8n8.x4.shared.b16 {%0,%1,%2,%3}, [%4];"
                    : "=r"(aH[mi][0]), "=r"(aH[mi][1]), "=r"(aH[mi][2]), "=r"(aH[mi][3])
                    : "r"(mb_ + aoff[mi] + koff));
            #pragma unroll
            for (int mi = 0; mi < 4; mi++)
                asm volatile("ldmatrix.sync.aligned.m8n8.x4.shared.b16 {%0,%1,%2,%3}, [%4];"
                    : "=r"(aL[mi][0]), "=r"(aL[mi][1]), "=r"(aL[mi][2]), "=r"(aL[mi][3])
                    : "r"(mb_ + MATB + aoff[mi] + koff));
            #pragma unroll
            for (int ni = 0; ni < 4; ni++)
                asm volatile("ldmatrix.sync.aligned.m8n8.x2.shared.b16 {%0,%1}, [%2];"
                    : "=r"(bH[ni][0]), "=r"(bH[ni][1])
                    : "r"(mb_ + 2*MATB + boff[ni] + koff));
            #pragma unroll
            for (int ni = 0; ni < 4; ni++)
                asm volatile("ldmatrix.sync.aligned.m8n8.x2.shared.b16 {%0,%1}, [%2];"
                    : "=r"(bL[ni][0]), "=r"(bL[ni][1])
                    : "r"(mb_ + 3*MATB + boff[ni] + koff));
            #pragma unroll
            for (int mi = 0; mi < 4; mi++)
                #pragma unroll
                for (int ni = 0; ni < 4; ni++) {
                    MMA_BF16(acc[mi][ni], aH[mi], bH[ni]);
                    MMA_BF16(acc[mi][ni], aH[mi], bL[ni]);
                    MMA_BF16(acc[mi][ni], aL[mi], bH[ni]);
                }
        }
        __syncthreads();
    }

    const int er = lane >> 2, ec = (lane & 3) * 2;
    if (mode == 0) {
        __nv_bfloat16* H = z ? g_kh : g_qh;
        __nv_bfloat16* L = z ? g_kl : g_ql;
        #pragma unroll
        for (int mi = 0; mi < 4; mi++)
            #pragma unroll
            for (int ni = 0; ni < 4; ni++)
                #pragma unroll
                for (int half = 0; half < 2; half++) {
                    size_t row = (size_t)(m0 + wm + mi * 16 + er + half * 8);
                    size_t col = (size_t)(n0 + wn + ni * 8 + ec);
                    float v0 = acc[mi][ni][half*2], v1 = acc[mi][ni][half*2+1];
                    __nv_bfloat16 h0 = __float2bfloat16(v0);
                    __nv_bfloat16 h1 = __float2bfloat16(v1);
                    *(__nv_bfloat162*)(H + row * NXC + col) = __nv_bfloat162(h0, h1);
                    *(__nv_bfloat162*)(L + row * NXC + col) = __nv_bfloat162(
                        __float2bfloat16(v0 - __bfloat162float(h0)),
                        __float2bfloat16(v1 - __bfloat162float(h1)));
                }
    } else {
        #pragma unroll
        for (int mi = 0; mi < 4; mi++)
            #pragma unroll
            for (int ni = 0; ni < 4; ni++) {
                size_t row = (size_t)(m0 + wm + mi * 16 + er);
                size_t col = (size_t)(n0 + wn + ni * 8 + ec);
                *(float2*)(g_v + row * NXC + col) =
                    make_float2(acc[mi][ni][0], acc[mi][ni][1]);
                *(float2*)(g_v + (row + 8) * NXC + col) =
                    make_float2(acc[mi][ni][2], acc[mi][ni][3]);
            }
    }
}

// ============ output GEMM, TM=64 tiles: 256 tiles, 2 CTA/SM ===============
#define O_AB (64*SST*2)          // 5120
#define O_BB (128*SST*2)         // 10240
#define O_STG (2*O_AB + 2*O_BB)  // 30720
#define O_SMEM (2*O_STG)         // 61440
__global__ void __launch_bounds__(256, 2) k_mma_out(float* __restrict__ outp)
{
    extern __shared__ __align__(16) char dsm[];
    const int tid = threadIdx.x, lane = tid & 31, wid = tid >> 5;
    const uint32_t sbase = smem_u32(dsm);

    int t = blockIdx.x;
    const int mb = t >> 2, nb = t & 3;
    const int m0 = mb * 64, n0 = nb * 128;
    const __nv_bfloat16* Bh = g_wh + (size_t)3 * NXC * NXC;
    const __nv_bfloat16* Bl = g_wl + (size_t)3 * NXC * NXC;

    const int lr = tid >> 2, lq = tid & 3;       // lr in [0,64)
    const uint32_t soA  = (uint32_t)(lr * SST + lq * 8) * 2;
    const uint32_t soB2 = soA + 64 * SST * 2;
    const size_t gA  = (size_t)(m0 + lr) * NXC + lq * 8;
    const size_t gB0 = (size_t)(n0 + lr) * NXC + lq * 8;
    const size_t gB1 = gB0 + (size_t)64 * NXC;

    const int wm = (wid >> 2) * 32;
    const int wn = (wid & 3) * 32;
    uint32_t aoff[2], boff[4];
    {
        int arow = wm + (lane & 15);
        int acol = ((lane >> 4) & 1) * 8;
        #pragma unroll
        for (int mi = 0; mi < 2; mi++)
            aoff[mi] = (uint32_t)((arow + mi * 16) * SST + acol) * 2;
        int l15 = lane & 15;
        int brow = wn + (l15 & 7);
        int bcol = ((l15 >> 3) & 1) * 8;
        #pragma unroll
        for (int ni = 0; ni < 4; ni++)
            boff[ni] = (uint32_t)((brow + ni * 8) * SST + bcol) * 2;
    }

    auto issue = [&](int ch, int p) {
        uint32_t s0 = sbase + (uint32_t)p * O_STG;
        int ko = ch * 32;
        CP16(s0 + soA,                  g_ah + gA + ko);
        CP16(s0 + O_AB + soA,           g_al + gA + ko);
        CP16(s0 + 2*O_AB + soA,         Bh + gB0 + ko);
        CP16(s0 + 2*O_AB + soB2,        Bh + gB1 + ko);
        CP16(s0 + 2*O_AB + O_BB + soA,  Bl + gB0 + ko);
        CP16(s0 + 2*O_AB + O_BB + soB2, Bl + gB1 + ko);
        asm volatile("cp.async.commit_group;" ::: "memory");
    };

    float acc[2][4][4];
    #pragma unroll
    for (int a = 0; a < 2; a++)
        #pragma unroll
        for (int b = 0; b < 4; b++)
            #pragma unroll
            for (int c = 0; c < 4; c++) acc[a][b][c] = 0.f;

    issue(0, 0);
    for (int ch = 0; ch < 16; ch++) {
        if (ch + 1 < 16) {
            issue(ch + 1, (ch + 1) & 1);
            asm volatile("cp.async.wait_group 1;" ::: "memory");
        } else {
            asm volatile("cp.async.wait_group 0;" ::: "memory");
        }
        __syncthreads();

        uint32_t mb_ = sbase + (uint32_t)(ch & 1) * O_STG;
        #pragma unroll
        for (int kk = 0; kk < 2; kk++) {
            uint32_t koff = (uint32_t)kk * 32;
            uint32_t aH[2][4], aL[2][4], bH[4][2], bL[4][2];
            #pragma unroll
            for (int mi = 0; mi < 2; mi++)
                asm volatile("ldmatrix.sync.aligned.m8n8.x4.shared.b16 {%0,%1,%2,%3}, [%4];"
                    : "=r"(aH[mi][0]), "=r"(aH[mi][1]), "=r"(aH[mi][2]), "=r"(aH[mi][3])
                    : "r"(mb_ + aoff[mi] + koff));
            #pragma unroll
            for (int mi = 0; mi < 2; mi++)
                asm volatile("ldmatrix.sync.aligned.m8n8.x4.shared.b16 {%0,%1,%2,%3}, [%4];"
                    : "=r"(aL[mi][0]), "=r"(aL[mi][1]), "=r"(aL[mi][2]), "=r"(aL[mi][3])
                    : "r"(mb_ + O_AB + aoff[mi] + koff));
            #pragma unroll
            for (int ni = 0; ni < 4; ni++)
                asm volatile("ldmatrix.sync.aligned.m8n8.x2.shared.b16 {%0,%1}, [%2];"
                    : "=r"(bH[ni][0]), "=r"(bH[ni][1])
                    : "r"(mb_ + 2*O_AB + boff[ni] + koff));
            #pragma unroll
            for (int ni = 0; ni < 4; ni++)
                asm volatile("ldmatrix.sync.aligned.m8n8.x2.shared.b16 {%0,%1}, [%2];"
                    : "=r"(bL[ni][0]), "=r"(bL[ni][1])
                    : "r"(mb_ + 2*O_AB + O_BB + boff[ni] + koff));
            #pragma unroll
            for (int mi = 0; mi < 2; mi++)
                #pragma unroll
                for (int ni = 0; ni < 4; ni++) {
                    MMA_BF16(acc[mi][ni], aH[mi], bH[ni]);
                    MMA_BF16(acc[mi][ni], aH[mi], bL[ni]);
                    MMA_BF16(acc[mi][ni], aL[mi], bH[ni]);
                }
        }
        __syncthreads();
    }

    const int er = lane >> 2, ec = (lane & 3) * 2;
    #pragma unroll
    for (int mi = 0; mi < 2; mi++)
        #pragma unroll
        for (int ni = 0; ni < 4; ni++) {
            size_t row = (size_t)(m0 + wm + mi * 16 + er);
            size_t col = (size_t)(n0 + wn + ni * 8 + ec);
            *(float2*)(outp + row * NXC + col) =
                make_float2(acc[mi][ni][0], acc[mi][ni][1]);
            *(float2*)(outp + (row + 8) * NXC + col) =
                make_float2(acc[mi][ni][2], acc[mi][ni][3]);
        }
}

// ============ HMMA w1/w2T: 12 gemms M=2048 N=64 K=128, heads 1..3 =========
#define W_AB (128*SST*2)
#define W_BB (64*SST*2)
#define W_STG (2*W_AB + 2*W_BB)
#define W_SMEM (2*W_STG)
__global__ void __launch_bounds__(256, 2) k_w12m()
{
    extern __shared__ __align__(16) char dsm[];
    const int tid = threadIdx.x, lane = tid & 31, wid = tid >> 5;
    const uint32_t sbase = smem_u32(dsm);

    int t = blockIdx.x;
    int g = t >> 4, mb = t & 15;
    int isw2 = (g >= 6);
    if (isw2) g -= 6;
    int b = g / 3, h = g % 3 + 1, bh = b * 4 + h;
    const __nv_bfloat16* AH = isw2 ? g_kh : g_qh;
    const __nv_bfloat16* AL = isw2 ? g_kl : g_ql;
    const __nv_bfloat16* BH = (isw2 ? g_sqh : g_skh) + (size_t)bh * LL * HD;
    const __nv_bfloat16* BL = (isw2 ? g_sql : g_skl) + (size_t)bh * LL * HD;
    float* C = (isw2 ? g_w2T : g_w1) + (size_t)bh * TT * LL;

    const int lr = tid >> 2, lq = tid & 3;
    const uint32_t soA  = (uint32_t)(lr * SST + lq * 8) * 2;
    const uint32_t soA2 = soA + 64 * SST * 2;
    const size_t gA0 = (size_t)(b * TT + mb * 128 + lr) * NXC + h * HD + lq * 8;
    const size_t gA1 = gA0 + (size_t)64 * NXC;
    const size_t gB  = (size_t)lr * HD + lq * 8;

    const int wm = (wid >> 2) * 64;
    const int wn = (wid & 3) * 16;
    uint32_t aoff[4], boff[2];
    {
        int arow = wm + (lane & 15);
        int acol = ((lane >> 4) & 1) * 8;
        #pragma unroll
        for (int mi = 0; mi < 4; mi++)
            aoff[mi] = (uint32_t)((arow + mi * 16) * SST + acol) * 2;
        int l15 = lane & 15;
        int brow = wn + (l15 & 7);
        int bcol = ((l15 >> 3) & 1) * 8;
        #pragma unroll
        for (int ni = 0; ni < 2; ni++)
            boff[ni] = (uint32_t)((brow + ni * 8) * SST + bcol) * 2;
    }

    auto issue = [&](int ch, int p) {
        uint32_t s0 = sbase + (uint32_t)p * W_STG;
        int ko = ch * 32;
        CP16(s0 + soA,                 AH + gA0 + ko);
        CP16(s0 + soA2,                AH + gA1 + ko);
        CP16(s0 + W_AB + soA,          AL + gA0 + ko);
        CP16(s0 + W_AB + soA2,         AL + gA1 + ko);
        CP16(s0 + 2*W_AB + soA,        BH + gB + ko);
        CP16(s0 + 2*W_AB + W_BB + soA, BL + gB + ko);
        asm volatile("cp.async.commit_group;" ::: "memory");
    };

    float acc[4][2][4];
    #pragma unroll
    for (int a = 0; a < 4; a++)
        #pragma unroll
        for (int b2 = 0; b2 < 2; b2++)
            #pragma unroll
            for (int c = 0; c < 4; c++) acc[a][b2][c] = 0.f;

    issue(0, 0);
    for (int ch = 0; ch < 4; ch++) {
        if (ch + 1 < 4) {
            issue(ch + 1, (ch + 1) & 1);
            asm volatile("cp.async.wait_group 1;" ::: "memory");
        } else {
            asm volatile("cp.async.wait_group 0;" ::: "memory");
        }
        __syncthreads();

        uint32_t mb_ = sbase + (uint32_t)(ch & 1) * W_STG;
        #pragma unroll
        for (int kk = 0; kk < 2; kk++) {
            uint32_t koff = (uint32_t)kk * 32;
            uint32_t aH[4][4], aL[4][4], bH[2][2], bL[2][2];
            #pragma unroll
            for (int mi = 0; mi < 4; mi++)
                asm volatile("ldmatrix.sync.aligned.m8n8.x4.shared.b16 {%0,%1,%2,%3}, [%4];"
                    : "=r"(aH[mi][0]), "=r"(aH[mi][1]), "=r"(aH[mi][2]), "=r"(aH[mi][3])
                    : "r"(mb_ + aoff[mi] + koff));
            #pragma unroll
            for (int mi = 0; mi < 4; mi++)
                asm volatile("ldmatrix.sync.aligned.m8n8.x4.shared.b16 {%0,%1,%2,%3}, [%4];"
                    : "=r"(aL[mi][0]), "=r"(aL[mi][1]), "=r"(aL[mi][2]), "=r"(aL[mi][3])
                    : "r"(mb_ + W_AB + aoff[mi] + koff));
            #pragma unroll
            for (int ni = 0; ni < 2; ni++)
                asm volatile("ldmatrix.sync.aligned.m8n8.x2.shared.b16 {%0,%1}, [%2];"
                    : "=r"(bH[ni][0]), "=r"(bH[ni][1])
                    : "r"(mb_ + 2*W_AB + boff[ni] + koff));
            #pragma unroll
            for (int ni = 0; ni < 2; ni++)
                asm volatile("ldmatrix.sync.aligned.m8n8.x2.shared.b16 {%0,%1}, [%2];"
                    : "=r"(bL[ni][0]), "=r"(bL[ni][1])
                    : "r"(mb_ + 2*W_AB + W_BB + boff[ni] + koff));
            #pragma unroll
            for (int mi = 0; mi < 4; mi++)
                #pragma unroll
                for (int ni = 0; ni < 2; ni++) {
                    MMA_BF16(acc[mi][ni], aH[mi], bH[ni]);
                    MMA_BF16(acc[mi][ni], aH[mi], bL[ni]);
                    MMA_BF16(acc[mi][ni], aL[mi], bH[ni]);
                }
        }
        __syncthreads();
    }

    const int er = lane >> 2, ec = (lane & 3) * 2;
    #pragma unroll
    for (int mi = 0; mi < 4; mi++)
        #pragma unroll
        for (int ni = 0; ni < 2; ni++) {
            size_t row = (size_t)(mb * 128 + wm + mi * 16 + er);
            size_t col = (size_t)(wn + ni * 8 + ec);
            *(float2*)(C + row * LL + col) = make_float2(acc[mi][ni][0], acc[mi][ni][1]);
            *(float2*)(C + (row + 8) * LL + col) = make_float2(acc[mi][ni][2], acc[mi][ni][3]);
        }
}

// ================= hi/lo bf16 split (x + weights) + vmean zero ============
__device__ __forceinline__ void split4(const float4 v, __nv_bfloat16* h, __nv_bfloat16* l, size_t i) {
    __nv_bfloat16 h0 = __float2bfloat16(v.x), h1 = __float2bfloat16(v.y);
    __nv_bfloat16 h2 = __float2bfloat16(v.z), h3 = __float2bfloat16(v.w);
    __nv_bfloat162* hp = (__nv_bfloat162*)(h + i);
    hp[0] = __nv_bfloat162(h0, h1); hp[1] = __nv_bfloat162(h2, h3);
    __nv_bfloat162* lp = (__nv_bfloat162*)(l + i);
    lp[0] = __nv_bfloat162(__float2bfloat16(v.x - __bfloat162float(h0)),
                           __float2bfloat16(v.y - __bfloat162float(h1)));
    lp[1] = __nv_bfloat162(__float2bfloat16(v.z - __bfloat162float(h2)),
                           __float2bfloat16(v.w - __bfloat162float(h3)));
}
__global__ void k_split_all(const float* __restrict__ x,
                            const float* __restrict__ wq, const float* __restrict__ wk,
                            const float* __restrict__ wv, const float* __restrict__ wo)
{
    int bid = blockIdx.x;
    if (bid < 4) g_vmean[bid * 256 + threadIdx.x] = 0.f;
    if (bid < 2048) {
        size_t i = ((size_t)bid * 256 + threadIdx.x) * 4;
        split4(*(const float4*)(x + i), g_xh, g_xl, i);
    } else {
        int r = bid - 2048;
        int z = r >> 8;
        const float* w = (z == 0) ? wq : (z == 1 ? wk : (z == 2 ? wv : wo));
        size_t i = ((size_t)(r & 255) * 256 + threadIdx.x) * 4;
        split4(*(const float4*)(w + i), g_wh + (size_t)z * NXC * NXC,
               g_wl + (size_t)z * NXC * NXC, i);
    }
}

// ---------------- landmark rows (heads 1..3) ------------------------------
__global__ void k_sqsk(const float* __restrict__ m1, const float* __restrict__ m2,
                       const int* __restrict__ lm)
{
    int r = blockIdx.x;
    int which = blockIdx.y;
    int b = r / 192, hh = (r / 64) % 3, l = r & 63;
    int h = hh + 1, bh = b * 4 + h;
    int tl = lm[l];
    size_t idx = ((size_t)b * TT + tl) * NXC + h * HD + threadIdx.x;
    float v = which == 0
        ? __bfloat162float(g_qh[idx]) + __bfloat162float(g_ql[idx])
        : __bfloat162float(g_kh[idx]) + __bfloat162float(g_kl[idx]);
    float ss = v * v;
    #pragma unroll
    for (int o=16;o;o>>=1) ss += __shfl_xor_sync(~0u,ss,o);
    __shared__ float sh[4];
    int d = threadIdx.x;
    if ((d&31)==0) sh[d>>5] = ss;
    __syncthreads();
    float tot = sh[0]+sh[1]+sh[2]+sh[3];
    float mval = (which==0 ? m1 : m2)[h*LL + l];
    float outv = v * rsqrtf(tot) * mval;
    __nv_bfloat16 oh = __float2bfloat16(outv);
    __nv_bfloat16 ol = __float2bfloat16(outv - __bfloat162float(oh));
    size_t o2 = (size_t)bh * LL * HD + l * HD + d;
    if (which == 0) { g_sqh[o2] = oh; g_sql[o2] = ol; }
    else            { g_skh[o2] = oh; g_skl[o2] = ol; }
}

// ---------------- mask bitmap + scalars fold ------------------------------
__global__ void k_mask_set(const int* __restrict__ rns,
                           const float* __restrict__ lq1, const float* __restrict__ lk1,
                           const float* __restrict__ lq2, const float* __restrict__ lk2,
                           const int* __restrict__ lp)
{
    int tid = threadIdx.x;
    int t = blockIdx.x * blockDim.x + tid;
    if (blockIdx.x == 0) {
        float v1 = 0.f, v2 = 0.f;
        if (tid < 128) { v1 = lq1[tid]*lk1[tid]; v2 = lq2[tid]*lk2[tid]; }
        #pragma unroll
        for (int o=16;o;o>>=1){ v1 += __shfl_xor_sync(~0u,v1,o); v2 += __shfl_xor_sync(~0u,v2,o); }
        __shared__ float s1[4], s2v[4];
        if (tid < 128 && (tid&31)==0) { s1[tid>>5]=v1; s2v[tid>>5]=v2; }
        __syncthreads();
        if (tid == 0) {
            float a  = s1[0]+s1[1]+s1[2]+s1[3];
            float b2 = s2v[0]+s2v[1]+s2v[2]+s2v[3];
            float li = 0.8f - 0.6f*expf(-0.3f * (float)lp[0]);
            g_lam_init = li;
            g_lam = expf(a) - expf(b2) + li;
        }
    }
    int b = t / (TT*KK);
    int i = (t / KK) % TT;
    int j = rns[t];
    atomicOr(&g_bits[((size_t)b*TT + i)*(TT/32) + (j>>5)], 1u << (j&31));
}
__global__ void k_mask(const int* __restrict__ rns)
{
    int gw = (blockIdx.x * blockDim.x + threadIdx.x) >> 5;
    if (gw >= BB*TT) return;
    int lane = threadIdx.x & 31;
    int b = gw / TT, i = gw % TT;
    const int* rowi = rns + ((size_t)b*TT + i)*KK;
    int j = rowi[lane];
    unsigned mm = __match_any_sync(0xffffffffu, j);
    bool first = ((mm & ((1u<<lane)-1u)) == 0u);
    bool hit = (g_bits[((size_t)b*TT + j)*(TT/32) + (i>>5)] >> (i&31)) & 1u;
    bool valid = first && hit;
    unsigned bal = __ballot_sync(0xffffffffu, valid);
    int pos = __popc(bal & ((1u<<lane)-1u));
    if (valid) g_rows[(size_t)gw*KK + pos] = j;
    if (lane==0) g_cnt[gw] = __popc(bal);
}

// ---------------- v column mean ----------------
__global__ void k_vmean()
{
    int b = blockIdx.x, seg = blockIdx.y, d = threadIdx.x;
    const float* vb = g_v + ((size_t)b*TT + seg*128)*NXC + d;
    float s = 0.f;
    #pragma unroll 4
    for (int t=0;t<128;t++) s += vb[(size_t)t*NXC];
    atomicAdd(&g_vmean[b*NXC + d], s * (1.f/(float)TT));
}

// ---------------- sparse softmax + AV + RMSNorm + bf16 split -------------
__global__ void k_sparse(const float* __restrict__ g)
{
    int row = blockIdx.x;
    int b = row >> 11, i = row & (TT-1);
    int tid = threadIdx.x;
    __shared__ int   s_j[KK];
    __shared__ float s_w1[3][LL];
    __shared__ float s_p[3][KK];
    __shared__ float s_c0[KK], s_c1[KK];
    __shared__ float s_r0[8], s_r1[8];
    int cnt = g_cnt[row];
    float lam = g_lam;
    float a0 = 0.f, a1 = 0.f;
    int d = tid;
    if (cnt == 0) {
        float c = 1.f - 2.f*lam;
        a0 = c * g_vmean[b*NXC + d];
        a1 = c * g_vmean[b*NXC + 256 + d];
    } else {
        if (tid < cnt) s_j[tid] = g_rows[(size_t)row*KK + tid];
        if (tid < 192) {
            int h = (tid >> 6) + 1, dd = tid & 63;
            s_w1[h-1][dd] = g_w1[((size_t)(b*4+h)*TT + i)*LL + dd];
        }
        __syncthreads();
        int w = tid >> 5, lane = tid & 31;
        if (w < 3) {
            float lg = -1e30f;
            if (lane < cnt) {
                const float* w2r = g_w2T + ((size_t)(b*4 + w + 1)*TT + s_j[lane])*LL;
                float s = 0.f;
                #pragma unroll
                for (int dd=0;dd<LL;dd++) s = fmaf(s_w1[w][dd], w2r[dd], s);
                lg = s;
            }
            float mx = lg;
            #pragma unroll
            for (int o=16;o;o>>=1) mx = fmaxf(mx, __shfl_xor_sync(~0u,mx,o));
            float ex = (lane < cnt) ? expf(lg - mx) : 0.f;
            float sm = ex;
            #pragma unroll
            for (int o=16;o;o>>=1) sm += __shfl_xor_sync(~0u,sm,o);
            if (lane < cnt) s_p[w][lane] = ex / sm;
        }
        __syncthreads();
        if (tid < cnt) {
            float p1 = s_p[0][tid], p2 = s_p[1][tid], p3 = s_p[2][tid];
            s_c0[tid] = -lam*p1 + (1.f-lam)*p2;
            s_c1[tid] =  p2 - p1 + (1.f-2.f*lam)*p3;
        }
        __syncthreads();
        const float* vb = g_v + (size_t)b*TT*NXC;
        for (int e=0;e<cnt;e++) {
            const float* vr = vb + (size_t)s_j[e]*NXC;
            a0 = fmaf(s_c0[e], vr[d],       a0);
            a1 = fmaf(s_c1[e], vr[256 + d], a1);
        }
    }
    float ss0 = a0*a0, ss1 = a1*a1;
    #pragma unroll
    for (int o=16;o;o>>=1){ ss0 += __shfl_xor_sync(~0u,ss0,o); ss1 += __shfl_xor_sync(~0u,ss1,o); }
    if ((tid&31)==0){ s_r0[tid>>5]=ss0; s_r1[tid>>5]=ss1; }
    __syncthreads();
    float t0=0.f, t1=0.f;
    #pragma unroll
    for (int q2=0;q2<8;q2++){ t0 += s_r0[q2]; t1 += s_r1[q2]; }
    float r0 = rsqrtf(t0*(1.f/256.f) + EPSC);
    float r1 = rsqrtf(t1*(1.f/256.f) + EPSC);
    float sc = 1.f - g_lam_init;
    float gg = g[d];
    float v0 = a0*r0*gg*sc;
    float v1 = a1*r1*gg*sc;
    size_t base = ((size_t)b*TT + i)*NXC;
    __nv_bfloat16 h0 = __float2bfloat16(v0);
    __nv_bfloat16 h1 = __float2bfloat16(v1);
    g_ah[base + d]       = h0;
    g_al[base + d]       = __float2bfloat16(v0 - __bfloat162float(h0));
    g_ah[base + 256 + d] = h1;
    g_al[base + 256 + d] = __float2bfloat16(v1 - __bfloat162float(h1));
}

// ---------------- launcher (multi-stream fork/join) ----------------------
extern "C" void kernel_launch(void* const* d_in, const int* in_sizes, int n_in,
                              void* d_out, int out_size)
{
    const float* x    = (const float*)d_in[0];
    const float* wq   = (const float*)d_in[1];
    const float* wk   = (const float*)d_in[2];
    const float* wv   = (const float*)d_in[3];
    const float* wo   = (const float*)d_in[4];
    const float* m1   = (const float*)d_in[5];
    const float* m2   = (const float*)d_in[6];
    const float* lq1  = (const float*)d_in[7];
    const float* lk1  = (const float*)d_in[8];
    const float* lq2  = (const float*)d_in[9];
    const float* lk2  = (const float*)d_in[10];
    const float* rmsg = (const float*)d_in[11];
    const int*   lp   = (const int*)d_in[12];
    const int*   rns  = (const int*)d_in[14];
    const int*   lm   = (const int*)d_in[15];
    float* out = (float*)d_out;

    static cudaStream_t s2 = nullptr, s3 = nullptr;
    static cudaEvent_t eS, e0, e2, e3;
    if (!s2) {
        cudaStreamCreateWithFlags(&s2, cudaStreamNonBlocking);
        cudaStreamCreateWithFlags(&s3, cudaStreamNonBlocking);
        cudaEventCreateWithFlags(&eS, cudaEventDisableTiming);
        cudaEventCreateWithFlags(&e0, cudaEventDisableTiming);
        cudaEventCreateWithFlags(&e2, cudaEventDisableTiming);
        cudaEventCreateWithFlags(&e3, cudaEventDisableTiming);
        cudaFuncSetAttribute(k_mma, cudaFuncAttributeMaxDynamicSharedMemorySize, SMEMB);
        cudaFuncSetAttribute(k_w12m, cudaFuncAttributeMaxDynamicSharedMemorySize, W_SMEM);
        cudaFuncSetAttribute(k_mma_out, cudaFuncAttributeMaxDynamicSharedMemorySize, O_SMEM);
    }

    // fork s3: mask chain + scalars (independent of everything else)
    cudaEventRecord(eS, 0);
    cudaStreamWaitEvent(s3, eS, 0);
    k_mask_set<<<BB*TT*KK/256, 256, 0, s3>>>(rns, lq1, lk1, lq2, lk2, lp);
    k_mask<<<(BB*TT)/8, 256, 0, s3>>>(rns);
    cudaEventRecord(e3, s3);

    // main: split, then fork s2 for v-projection + vmean
    k_split_all<<<3072, 256>>>(x, wq, wk, wv, wo);
    cudaEventRecord(e0, 0);
    cudaStreamWaitEvent(s2, e0, 0);
    k_mma<<<128, 256, SMEMB, s2>>>(2, nullptr);          // v projection
    k_vmean<<<dim3(BB, TT/128), NXC, 0, s2>>>();
    cudaEventRecord(e2, s2);

    // main: qk projection -> landmarks -> w1/w2
    k_mma<<<192, 256, SMEMB>>>(0, nullptr);              // q,k projection
    k_sqsk<<<dim3(384, 2), 128>>>(m1, m2, lm);
    k_w12m<<<192, 256, W_SMEM>>>();

    // join
    cudaStreamWaitEvent(0, e2, 0);
    cudaStreamWaitEvent(0, e3, 0);
    k_sparse<<<BB*TT, 256>>>(rmsg);
    k_mma_out<<<256, 256, O_SMEM>>>(out);
}

// round 13
// speedup vs baseline: 1.8384x; 1.0500x over previous
#include <cuda_runtime.h>
#include <cuda_bf16.h>
#include <math.h>
#include <stdint.h>

#define BB   2
#define TT   2048
#define NXC  512
#define HD   128
#define LL   64
#define KK   32
#define EPSC 1e-5f

// ---------------- device scratch ----------------
__device__ float g_v[BB*TT*NXC];
__device__ float g_w1 [BB*4*TT*LL];
__device__ float g_w2T[BB*4*TT*LL];
__device__ float g_vmean[BB*NXC];
__device__ int   g_cnt [BB*TT];
__device__ int   g_rows[BB*TT*KK];
__device__ float g_lam, g_lam_init;
__device__ __nv_bfloat16 g_xh[BB*TT*NXC];
__device__ __nv_bfloat16 g_xl[BB*TT*NXC];
__device__ __nv_bfloat16 g_wh[4*NXC*NXC];
__device__ __nv_bfloat16 g_wl[4*NXC*NXC];
__device__ __nv_bfloat16 g_ah[BB*TT*NXC];
__device__ __nv_bfloat16 g_al[BB*TT*NXC];
__device__ __nv_bfloat16 g_qh[BB*TT*NXC];
__device__ __nv_bfloat16 g_ql[BB*TT*NXC];
__device__ __nv_bfloat16 g_kh[BB*TT*NXC];
__device__ __nv_bfloat16 g_kl[BB*TT*NXC];
__device__ __nv_bfloat16 g_sqh[8*LL*HD], g_sql[8*LL*HD];
__device__ __nv_bfloat16 g_skh[8*LL*HD], g_skl[8*LL*HD];
__device__ unsigned g_bits[BB*TT*(TT/32)];

__device__ __forceinline__ uint32_t smem_u32(const void* p) {
    uint32_t a;
    asm("{ .reg .u64 t; cvta.to.shared.u64 t, %1; cvt.u32.u64 %0, t; }" : "=r"(a) : "l"(p));
    return a;
}
#define CP16(dst, src) \
    asm volatile("cp.async.cg.shared.global [%0], [%1], 16;" :: "r"(dst), "l"(src))
#define MMA_BF16(acc, a, b) \
    asm volatile("mma.sync.aligned.m16n8k16.row.col.f32.bf16.bf16.f32 " \
        "{%0,%1,%2,%3}, {%4,%5,%6,%7}, {%8,%9}, {%0,%1,%2,%3};" \
        : "+f"((acc)[0]), "+f"((acc)[1]), "+f"((acc)[2]), "+f"((acc)[3]) \
        : "r"((a)[0]), "r"((a)[1]), "r"((a)[2]), "r"((a)[3]), "r"((b)[0]), "r"((b)[1]))

// ============ HMMA split-bf16 GEMM, single-barrier pipeline ===============
// mode 0: qk projection (192 tiles, z in {0,1}, nb in {1,2,3})
// mode 2: v projection  (128 tiles, z=2) + fused vmean
#define SST  40
#define MATB (128*SST*2)
#define BUFB (4*MATB)
#define SMEMB (2*BUFB)
__global__ void __launch_bounds__(256, 2) k_mma(int mode, float* __restrict__ outp)
{
    extern __shared__ __align__(16) char dsm[];
    const int tid = threadIdx.x, lane = tid & 31, wid = tid >> 5;
    const uint32_t sbase = smem_u32(dsm);

    const int lr = tid >> 2, lq = tid & 3;
    const uint32_t so  = (uint32_t)(lr * SST + lq * 8) * 2;
    const uint32_t so2 = so + 64 * SST * 2;

    const int wm = (wid >> 2) * 64;
    const int wn = (wid & 3) * 32;
    uint32_t aoff[4], boff[4];
    {
        int arow = wm + (lane & 15);
        int acol = ((lane >> 4) & 1) * 8;
        #pragma unroll
        for (int mi = 0; mi < 4; mi++)
            aoff[mi] = (uint32_t)((arow + mi * 16) * SST + acol) * 2;
        int l15 = lane & 15;
        int brow = wn + (l15 & 7);
        int bcol = ((l15 >> 3) & 1) * 8;
        #pragma unroll
        for (int ni = 0; ni < 4; ni++)
            boff[ni] = (uint32_t)((brow + ni * 8) * SST + bcol) * 2;
    }

    int t = blockIdx.x;
    int z, mb, nb;
    if (mode == 0) { z = t / 96; int r = t % 96; nb = r % 3 + 1; mb = r / 3; }
    else           { z = 2; nb = t & 3; mb = t >> 2; }
    const int m0 = mb * 128, n0 = nb * 128;
    const __nv_bfloat16* Bh = g_wh + (size_t)z * NXC * NXC;
    const __nv_bfloat16* Bl = g_wl + (size_t)z * NXC * NXC;

    const size_t gA0 = (size_t)(m0 + lr) * NXC + lq * 8;
    const size_t gA1 = gA0 + (size_t)64 * NXC;
    const size_t gB0 = (size_t)(n0 + lr) * NXC + lq * 8;
    const size_t gB1 = gB0 + (size_t)64 * NXC;

    auto issue = [&](int ch, int p) {
        uint32_t s0 = sbase + (uint32_t)p * BUFB;
        int ko = ch * 32;
        CP16(s0 + so,           g_xh + gA0 + ko);
        CP16(s0 + so2,          g_xh + gA1 + ko);
        CP16(s0 + MATB + so,    g_xl + gA0 + ko);
        CP16(s0 + MATB + so2,   g_xl + gA1 + ko);
        CP16(s0 + 2*MATB + so,  Bh + gB0 + ko);
        CP16(s0 + 2*MATB + so2, Bh + gB1 + ko);
        CP16(s0 + 3*MATB + so,  Bl + gB0 + ko);
        CP16(s0 + 3*MATB + so2, Bl + gB1 + ko);
        asm volatile("cp.async.commit_group;" ::: "memory");
    };

    float acc[4][4][4];
    #pragma unroll
    for (int a = 0; a < 4; a++)
        #pragma unroll
        for (int b = 0; b < 4; b++)
            #pragma unroll
            for (int c = 0; c < 4; c++) acc[a][b][c] = 0.f;

    issue(0, 0);
    for (int ch = 0; ch < 16; ch++) {
        asm volatile("cp.async.wait_group 0;" ::: "memory");
        __syncthreads();
        if (ch + 1 < 16) issue(ch + 1, (ch + 1) & 1);

        uint32_t mb_ = sbase + (uint32_t)(ch & 1) * BUFB;
        #pragma unroll
        for (int kk = 0; kk < 2; kk++) {
            uint32_t koff = (uint32_t)kk * 32;
            uint32_t aH[4][4], aL[4][4], bH[4][2], bL[4][2];
            #pragma unroll
            for (int mi = 0; mi < 4; mi++)
                asm volatile("ldmatrix.sync.aligned.m8n8.x4.shared.b16 {%0,%1,%2,%3}, [%4];"
                    : "=r"(aH[mi][0]), "=r"(aH[mi][1]), "=r"(aH[mi][2]), "=r"(aH[mi][3])
                    : "r"(mb_ + aoff[mi] + koff));
            #pragma unroll
            for (int mi = 0; mi < 4; mi++)
                asm volatile("ldmatrix.sync.aligned.m8n8.x4.shared.b16 {%0,%1,%2,%3}, [%4];"
                    : "=r"(aL[mi][0]), "=r"(aL[mi][1]), "=r"(aL[mi][2]), "=r"(aL[mi][3])
                    : "r"(mb_ + MATB + aoff[mi] + koff));
            #pragma unroll
            for (int ni = 0; ni < 4; ni++)
                asm volatile("ldmatrix.sync.aligned.m8n8.x2.shared.b16 {%0,%1}, [%2];"
                    : "=r"(bH[ni][0]), "=r"(bH[ni][1])
                    : "r"(mb_ + 2*MATB + boff[ni] + koff));
            #pragma unroll
            for (int ni = 0; ni < 4; ni++)
                asm volatile("ldmatrix.sync.aligned.m8n8.x2.shared.b16 {%0,%1}, [%2];"
                    : "=r"(bL[ni][0]), "=r"(bL[ni][1])
                    : "r"(mb_ + 3*MATB + boff[ni] + koff));
            #pragma unroll
            for (int mi = 0; mi < 4; mi++)
                #pragma unroll
                for (int ni = 0; ni < 4; ni++) {
                    MMA_BF16(acc[mi][ni], aH[mi], bH[ni]);
                    MMA_BF16(acc[mi][ni], aH[mi], bL[ni]);
                    MMA_BF16(acc[mi][ni], aL[mi], bH[ni]);
                }
        }
    }

    const int er = lane >> 2, ec = (lane & 3) * 2;
    if (mode == 0) {
        __nv_bfloat16* H = z ? g_kh : g_qh;
        __nv_bfloat16* L = z ? g_kl : g_ql;
        #pragma unroll
        for (int mi = 0; mi < 4; mi++)
            #pragma unroll
            for (int ni = 0; ni < 4; ni++)
                #pragma unroll
                for (int half = 0; half < 2; half++) {
                    size_t row = (size_t)(m0 + wm + mi * 16 + er + half * 8);
                    size_t col = (size_t)(n0 + wn + ni * 8 + ec);
                    float v0 = acc[mi][ni][half*2], v1 = acc[mi][ni][half*2+1];
                    __nv_bfloat16 h0 = __float2bfloat16(v0);
                    __nv_bfloat16 h1 = __float2bfloat16(v1);
                    *(__nv_bfloat162*)(H + row * NXC + col) = __nv_bfloat162(h0, h1);
                    *(__nv_bfloat162*)(L + row * NXC + col) = __nv_bfloat162(
                        __float2bfloat16(v0 - __bfloat162float(h0)),
                        __float2bfloat16(v1 - __bfloat162float(h1)));
                }
    } else {
        #pragma unroll
        for (int mi = 0; mi < 4; mi++)
            #pragma unroll
            for (int ni = 0; ni < 4; ni++) {
                size_t row = (size_t)(m0 + wm + mi * 16 + er);
                size_t col = (size_t)(n0 + wn + ni * 8 + ec);
                *(float2*)(g_v + row * NXC + col) =
                    make_float2(acc[mi][ni][0], acc[mi][ni][1]);
                *(float2*)(g_v + (row + 8) * NXC + col) =
                    make_float2(acc[mi][ni][2], acc[mi][ni][3]);
            }
        // fused vmean: column sums of this tile's 128 rows
        int b = m0 >> 11;
        #pragma unroll
        for (int ni = 0; ni < 4; ni++) {
            float s0 = 0.f, s1 = 0.f;
            #pragma unroll
            for (int mi = 0; mi < 4; mi++) {
                s0 += acc[mi][ni][0] + acc[mi][ni][2];
                s1 += acc[mi][ni][1] + acc[mi][ni][3];
            }
            #pragma unroll
            for (int o = 16; o >= 4; o >>= 1) {
                s0 += __shfl_xor_sync(~0u, s0, o);
                s1 += __shfl_xor_sync(~0u, s1, o);
            }
            if (lane < 4) {
                int col = n0 + wn + ni * 8 + lane * 2;
                atomicAdd(&g_vmean[b * NXC + col],     s0 * (1.f/(float)TT));
                atomicAdd(&g_vmean[b * NXC + col + 1], s1 * (1.f/(float)TT));
            }
        }
    }
}

// ============ output GEMM, TM=64 tiles, single-barrier pipeline ===========
#define O_AB (64*SST*2)
#define O_BB (128*SST*2)
#define O_STG (2*O_AB + 2*O_BB)
#define O_SMEM (2*O_STG)
__global__ void __launch_bounds__(256, 2) k_mma_out(float* __restrict__ outp)
{
    extern __shared__ __align__(16) char dsm[];
    const int tid = threadIdx.x, lane = tid & 31, wid = tid >> 5;
    const uint32_t sbase = smem_u32(dsm);

    int t = blockIdx.x;
    const int mb = t >> 2, nb = t & 3;
    const int m0 = mb * 64, n0 = nb * 128;
    const __nv_bfloat16* Bh = g_wh + (size_t)3 * NXC * NXC;
    const __nv_bfloat16* Bl = g_wl + (size_t)3 * NXC * NXC;

    const int lr = tid >> 2, lq = tid & 3;
    const uint32_t soA  = (uint32_t)(lr * SST + lq * 8) * 2;
    const uint32_t soB2 = soA + 64 * SST * 2;
    const size_t gA  = (size_t)(m0 + lr) * NXC + lq * 8;
    const size_t gB0 = (size_t)(n0 + lr) * NXC + lq * 8;
    const size_t gB1 = gB0 + (size_t)64 * NXC;

    const int wm = (wid >> 2) * 32;
    const int wn = (wid & 3) * 32;
    uint32_t aoff[2], boff[4];
    {
        int arow = wm + (lane & 15);
        int acol = ((lane >> 4) & 1) * 8;
        #pragma unroll
        for (int mi = 0; mi < 2; mi++)
            aoff[mi] = (uint32_t)((arow + mi * 16) * SST + acol) * 2;
        int l15 = lane & 15;
        int brow = wn + (l15 & 7);
        int bcol = ((l15 >> 3) & 1) * 8;
        #pragma unroll
        for (int ni = 0; ni < 4; ni++)
            boff[ni] = (uint32_t)((brow + ni * 8) * SST + bcol) * 2;
    }

    auto issue = [&](int ch, int p) {
        uint32_t s0 = sbase + (uint32_t)p * O_STG;
        int ko = ch * 32;
        CP16(s0 + soA,                  g_ah + gA + ko);
        CP16(s0 + O_AB + soA,           g_al + gA + ko);
        CP16(s0 + 2*O_AB + soA,         Bh + gB0 + ko);
        CP16(s0 + 2*O_AB + soB2,        Bh + gB1 + ko);
        CP16(s0 + 2*O_AB + O_BB + soA,  Bl + gB0 + ko);
        CP16(s0 + 2*O_AB + O_BB + soB2, Bl + gB1 + ko);
        asm volatile("cp.async.commit_group;" ::: "memory");
    };

    float acc[2][4][4];
    #pragma unroll
    for (int a = 0; a < 2; a++)
        #pragma unroll
        for (int b = 0; b < 4; b++)
            #pragma unroll
            for (int c = 0; c < 4; c++) acc[a][b][c] = 0.f;

    issue(0, 0);
    for (int ch = 0; ch < 16; ch++) {
        asm volatile("cp.async.wait_group 0;" ::: "memory");
        __syncthreads();
        if (ch + 1 < 16) issue(ch + 1, (ch + 1) & 1);

        uint32_t mb_ = sbase + (uint32_t)(ch & 1) * O_STG;
        #pragma unroll
        for (int kk = 0; kk < 2; kk++) {
            uint32_t koff = (uint32_t)kk * 32;
            uint32_t aH[2][4], aL[2][4], bH[4][2], bL[4][2];
            #pragma unroll
            for (int mi = 0; mi < 2; mi++)
                asm volatile("ldmatrix.sync.aligned.m8n8.x4.shared.b16 {%0,%1,%2,%3}, [%4];"
                    : "=r"(aH[mi][0]), "=r"(aH[mi][1]), "=r"(aH[mi][2]), "=r"(aH[mi][3])
                    : "r"(mb_ + aoff[mi] + koff));
            #pragma unroll
            for (int mi = 0; mi < 2; mi++)
                asm volatile("ldmatrix.sync.aligned.m8n8.x4.shared.b16 {%0,%1,%2,%3}, [%4];"
                    : "=r"(aL[mi][0]), "=r"(aL[mi][1]), "=r"(aL[mi][2]), "=r"(aL[mi][3])
                    : "r"(mb_ + O_AB + aoff[mi] + koff));
            #pragma unroll
            for (int ni = 0; ni < 4; ni++)
                asm volatile("ldmatrix.sync.aligned.m8n8.x2.shared.b16 {%0,%1}, [%2];"
                    : "=r"(bH[ni][0]), "=r"(bH[ni][1])
                    : "r"(mb_ + 2*O_AB + boff[ni] + koff));
            #pragma unroll
            for (int ni = 0; ni < 4; ni++)
                asm volatile("ldmatrix.sync.aligned.m8n8.x2.shared.b16 {%0,%1}, [%2];"
                    : "=r"(bL[ni][0]), "=r"(bL[ni][1])
                    : "r"(mb_ + 2*O_AB + O_BB + boff[ni] + koff));
            #pragma unroll
            for (int mi = 0; mi < 2; mi++)
                #pragma unroll
                for (int ni = 0; ni < 4; ni++) {
                    MMA_BF16(acc[mi][ni], aH[mi], bH[ni]);
                    MMA_BF16(acc[mi][ni], aH[mi], bL[ni]);
                    MMA_BF16(acc[mi][ni], aL[mi], bH[ni]);
                }
        }
    }

    const int er = lane >> 2, ec = (lane & 3) * 2;
    #pragma unroll
    for (int mi = 0; mi < 2; mi++)
        #pragma unroll
        for (int ni = 0; ni < 4; ni++) {
            size_t row = (size_t)(m0 + wm + mi * 16 + er);
            size_t col = (size_t)(n0 + wn + ni * 8 + ec);
            *(float2*)(outp + row * NXC + col) =
                make_float2(acc[mi][ni][0], acc[mi][ni][1]);
            *(float2*)(outp + (row + 8) * NXC + col) =
                make_float2(acc[mi][ni][2], acc[mi][ni][3]);
        }
}

// ============ HMMA w1/w2T: 12 gemms M=2048 N=64 K=128 =====================
#define W_AB (128*SST*2)
#define W_BB (64*SST*2)
#define W_STG (2*W_AB + 2*W_BB)
#define W_SMEM (2*W_STG)
__global__ void __launch_bounds__(256, 2) k_w12m()
{
    extern __shared__ __align__(16) char dsm[];
    const int tid = threadIdx.x, lane = tid & 31, wid = tid >> 5;
    const uint32_t sbase = smem_u32(dsm);

    int t = blockIdx.x;
    int g = t >> 4, mb = t & 15;
    int isw2 = (g >= 6);
    if (isw2) g -= 6;
    int b = g / 3, h = g % 3 + 1, bh = b * 4 + h;
    const __nv_bfloat16* AH = isw2 ? g_kh : g_qh;
    const __nv_bfloat16* AL = isw2 ? g_kl : g_ql;
    const __nv_bfloat16* BH = (isw2 ? g_sqh : g_skh) + (size_t)bh * LL * HD;
    const __nv_bfloat16* BL = (isw2 ? g_sql : g_skl) + (size_t)bh * LL * HD;
    float* C = (isw2 ? g_w2T : g_w1) + (size_t)bh * TT * LL;

    const int lr = tid >> 2, lq = tid & 3;
    const uint32_t soA  = (uint32_t)(lr * SST + lq * 8) * 2;
    const uint32_t soA2 = soA + 64 * SST * 2;
    const size_t gA0 = (size_t)(b * TT + mb * 128 + lr) * NXC + h * HD + lq * 8;
    const size_t gA1 = gA0 + (size_t)64 * NXC;
    const size_t gB  = (size_t)lr * HD + lq * 8;

    const int wm = (wid >> 2) * 64;
    const int wn = (wid & 3) * 16;
    uint32_t aoff[4], boff[2];
    {
        int arow = wm + (lane & 15);
        int acol = ((lane >> 4) & 1) * 8;
        #pragma unroll
        for (int mi = 0; mi < 4; mi++)
            aoff[mi] = (uint32_t)((arow + mi * 16) * SST + acol) * 2;
        int l15 = lane & 15;
        int brow = wn + (l15 & 7);
        int bcol = ((l15 >> 3) & 1) * 8;
        #pragma unroll
        for (int ni = 0; ni < 2; ni++)
            boff[ni] = (uint32_t)((brow + ni * 8) * SST + bcol) * 2;
    }

    auto issue = [&](int ch, int p) {
        uint32_t s0 = sbase + (uint32_t)p * W_STG;
        int ko = ch * 32;
        CP16(s0 + soA,                 AH + gA0 + ko);
        CP16(s0 + soA2,                AH + gA1 + ko);
        CP16(s0 + W_AB + soA,          AL + gA0 + ko);
        CP16(s0 + W_AB + soA2,         AL + gA1 + ko);
        CP16(s0 + 2*W_AB + soA,        BH + gB + ko);
        CP16(s0 + 2*W_AB + W_BB + soA, BL + gB + ko);
        asm volatile("cp.async.commit_group;" ::: "memory");
    };

    float acc[4][2][4];
    #pragma unroll
    for (int a = 0; a < 4; a++)
        #pragma unroll
        for (int b2 = 0; b2 < 2; b2++)
            #pragma unroll
            for (int c = 0; c < 4; c++) acc[a][b2][c] = 0.f;

    issue(0, 0);
    for (int ch = 0; ch < 4; ch++) {
        asm volatile("cp.async.wait_group 0;" ::: "memory");
        __syncthreads();
        if (ch + 1 < 4) issue(ch + 1, (ch + 1) & 1);

        uint32_t mb_ = sbase + (uint32_t)(ch & 1) * W_STG;
        #pragma unroll
        for (int kk = 0; kk < 2; kk++) {
            uint32_t koff = (uint32_t)kk * 32;
            uint32_t aH[4][4], aL[4][4], bH[2][2], bL[2][2];
            #pragma unroll
            for (int mi = 0; mi < 4; mi++)
                asm volatile("ldmatrix.sync.aligned.m8n8.x4.shared.b16 {%0,%1,%2,%3}, [%4];"
                    : "=r"(aH[mi][0]), "=r"(aH[mi][1]), "=r"(aH[mi][2]), "=r"(aH[mi][3])
                    : "r"(mb_ + aoff[mi] + koff));
            #pragma unroll
            for (int mi = 0; mi < 4; mi++)
                asm volatile("ldmatrix.sync.aligned.m8n8.x4.shared.b16 {%0,%1,%2,%3}, [%4];"
                    : "=r"(aL[mi][0]), "=r"(aL[mi][1]), "=r"(aL[mi][2]), "=r"(aL[mi][3])
                    : "r"(mb_ + W_AB + aoff[mi] + koff));
            #pragma unroll
            for (int ni = 0; ni < 2; ni++)
                asm volatile("ldmatrix.sync.aligned.m8n8.x2.shared.b16 {%0,%1}, [%2];"
                    : "=r"(bH[ni][0]), "=r"(bH[ni][1])
                    : "r"(mb_ + 2*W_AB + boff[ni] + koff));
            #pragma unroll
            for (int ni = 0; ni < 2; ni++)
                asm volatile("ldmatrix.sync.aligned.m8n8.x2.shared.b16 {%0,%1}, [%2];"
                    : "=r"(bL[ni][0]), "=r"(bL[ni][1])
                    : "r"(mb_ + 2*W_AB + W_BB + boff[ni] + koff));
            #pragma unroll
            for (int mi = 0; mi < 4; mi++)
                #pragma unroll
                for (int ni = 0; ni < 2; ni++) {
                    MMA_BF16(acc[mi][ni], aH[mi], bH[ni]);
                    MMA_BF16(acc[mi][ni], aH[mi], bL[ni]);
                    MMA_BF16(acc[mi][ni], aL[mi], bH[ni]);
                }
        }
    }

    const int er = lane >> 2, ec = (lane & 3) * 2;
    #pragma unroll
    for (int mi = 0; mi < 4; mi++)
        #pragma unroll
        for (int ni = 0; ni < 2; ni++) {
            size_t row = (size_t)(mb * 128 + wm + mi * 16 + er);
            size_t col = (size_t)(wn + ni * 8 + ec);
            *(float2*)(C + row * LL + col) = make_float2(acc[mi][ni][0], acc[mi][ni][1]);
            *(float2*)(C + (row + 8) * LL + col) = make_float2(acc[mi][ni][2], acc[mi][ni][3]);
        }
}

// ================= hi/lo bf16 split (x + weights) + vmean zero ============
__device__ __forceinline__ void split4(const float4 v, __nv_bfloat16* h, __nv_bfloat16* l, size_t i) {
    __nv_bfloat16 h0 = __float2bfloat16(v.x), h1 = __float2bfloat16(v.y);
    __nv_bfloat16 h2 = __float2bfloat16(v.z), h3 = __float2bfloat16(v.w);
    __nv_bfloat162* hp = (__nv_bfloat162*)(h + i);
    hp[0] = __nv_bfloat162(h0, h1); hp[1] = __nv_bfloat162(h2, h3);
    __nv_bfloat162* lp = (__nv_bfloat162*)(l + i);
    lp[0] = __nv_bfloat162(__float2bfloat16(v.x - __bfloat162float(h0)),
                           __float2bfloat16(v.y - __bfloat162float(h1)));
    lp[1] = __nv_bfloat162(__float2bfloat16(v.z - __bfloat162float(h2)),
                           __float2bfloat16(v.w - __bfloat162float(h3)));
}
__global__ void k_split_all(const float* __restrict__ x,
                            const float* __restrict__ wq, const float* __restrict__ wk,
                            const float* __restrict__ wv, const float* __restrict__ wo)
{
    int bid = blockIdx.x;
    if (bid < 4) g_vmean[bid * 256 + threadIdx.x] = 0.f;
    if (bid < 2048) {
        size_t i = ((size_t)bid * 256 + threadIdx.x) * 4;
        split4(*(const float4*)(x + i), g_xh, g_xl, i);
    } else {
        int r = bid - 2048;
        int z = r >> 8;
        const float* w = (z == 0) ? wq : (z == 1 ? wk : (z == 2 ? wv : wo));
        size_t i = ((size_t)(r & 255) * 256 + threadIdx.x) * 4;
        split4(*(const float4*)(w + i), g_wh + (size_t)z * NXC * NXC,
               g_wl + (size_t)z * NXC * NXC, i);
    }
}

// ---------------- landmark rows (heads 1..3) ------------------------------
__global__ void k_sqsk(const float* __restrict__ m1, const float* __restrict__ m2,
                       const int* __restrict__ lm)
{
    int r = blockIdx.x;
    int which = blockIdx.y;
    int b = r / 192, hh = (r / 64) % 3, l = r & 63;
    int h = hh + 1, bh = b * 4 + h;
    int tl = lm[l];
    size_t idx = ((size_t)b * TT + tl) * NXC + h * HD + threadIdx.x;
    float v = which == 0
        ? __bfloat162float(g_qh[idx]) + __bfloat162float(g_ql[idx])
        : __bfloat162float(g_kh[idx]) + __bfloat162float(g_kl[idx]);
    float ss = v * v;
    #pragma unroll
    for (int o=16;o;o>>=1) ss += __shfl_xor_sync(~0u,ss,o);
    __shared__ float sh[4];
    int d = threadIdx.x;
    if ((d&31)==0) sh[d>>5] = ss;
    __syncthreads();
    float tot = sh[0]+sh[1]+sh[2]+sh[3];
    float mval = (which==0 ? m1 : m2)[h*LL + l];
    float outv = v * rsqrtf(tot) * mval;
    __nv_bfloat16 oh = __float2bfloat16(outv);
    __nv_bfloat16 ol = __float2bfloat16(outv - __bfloat162float(oh));
    size_t o2 = (size_t)bh * LL * HD + l * HD + d;
    if (which == 0) { g_sqh[o2] = oh; g_sql[o2] = ol; }
    else            { g_skh[o2] = oh; g_skl[o2] = ol; }
}

// ---------------- mask bitmap + scalars fold ------------------------------
__global__ void k_mask_set(const int* __restrict__ rns,
                           const float* __restrict__ lq1, const float* __restrict__ lk1,
                           const float* __restrict__ lq2, const float* __restrict__ lk2,
                           const int* __restrict__ lp)
{
    int tid = threadIdx.x;
    int t = blockIdx.x * blockDim.x + tid;
    if (blockIdx.x == 0) {
        float v1 = 0.f, v2 = 0.f;
        if (tid < 128) { v1 = lq1[tid]*lk1[tid]; v2 = lq2[tid]*lk2[tid]; }
        #pragma unroll
        for (int o=16;o;o>>=1){ v1 += __shfl_xor_sync(~0u,v1,o); v2 += __shfl_xor_sync(~0u,v2,o); }
        __shared__ float s1[4], s2v[4];
        if (tid < 128 && (tid&31)==0) { s1[tid>>5]=v1; s2v[tid>>5]=v2; }
        __syncthreads();
        if (tid == 0) {
            float a  = s1[0]+s1[1]+s1[2]+s1[3];
            float b2 = s2v[0]+s2v[1]+s2v[2]+s2v[3];
            float li = 0.8f - 0.6f*expf(-0.3f * (float)lp[0]);
            g_lam_init = li;
            g_lam = expf(a) - expf(b2) + li;
        }
    }
    int b = t / (TT*KK);
    int i = (t / KK) % TT;
    int j = rns[t];
    atomicOr(&g_bits[((size_t)b*TT + i)*(TT/32) + (j>>5)], 1u << (j&31));
}
__global__ void k_mask(const int* __restrict__ rns)
{
    int gw = (blockIdx.x * blockDim.x + threadIdx.x) >> 5;
    if (gw >= BB*TT) return;
    int lane = threadIdx.x & 31;
    int b = gw / TT, i = gw % TT;
    const int* rowi = rns + ((size_t)b*TT + i)*KK;
    int j = rowi[lane];
    unsigned mm = __match_any_sync(0xffffffffu, j);
    bool first = ((mm & ((1u<<lane)-1u)) == 0u);
    bool hit = (g_bits[((size_t)b*TT + j)*(TT/32) + (i>>5)] >> (i&31)) & 1u;
    bool valid = first && hit;
    unsigned bal = __ballot_sync(0xffffffffu, valid);
    int pos = __popc(bal & ((1u<<lane)-1u));
    if (valid) g_rows[(size_t)gw*KK + pos] = j;
    if (lane==0) g_cnt[gw] = __popc(bal);
}

// ---------------- sparse softmax + AV + RMSNorm + bf16 split -------------
__global__ void k_sparse(const float* __restrict__ g)
{
    int row = blockIdx.x;
    int b = row >> 11, i = row & (TT-1);
    int tid = threadIdx.x;
    __shared__ int   s_j[KK];
    __shared__ float s_w1[3][LL];
    __shared__ float s_p[3][KK];
    __shared__ float s_c0[KK], s_c1[KK];
    __shared__ float s_r0[8], s_r1[8];
    int cnt = g_cnt[row];
    float lam = g_lam;
    float a0 = 0.f, a1 = 0.f;
    int d = tid;
    if (cnt == 0) {
        float c = 1.f - 2.f*lam;
        a0 = c * g_vmean[b*NXC + d];
        a1 = c * g_vmean[b*NXC + 256 + d];
    } else {
        if (tid < cnt) s_j[tid] = g_rows[(size_t)row*KK + tid];
        if (tid < 192) {
            int h = (tid >> 6) + 1, dd = tid & 63;
            s_w1[h-1][dd] = g_w1[((size_t)(b*4+h)*TT + i)*LL + dd];
        }
        __syncthreads();
        int w = tid >> 5, lane = tid & 31;
        if (w < 3) {
            float lg = -1e30f;
            if (lane < cnt) {
                const float* w2r = g_w2T + ((size_t)(b*4 + w + 1)*TT + s_j[lane])*LL;
                float s = 0.f;
                #pragma unroll
                for (int dd=0;dd<LL;dd++) s = fmaf(s_w1[w][dd], w2r[dd], s);
                lg = s;
            }
            float mx = lg;
            #pragma unroll
            for (int o=16;o;o>>=1) mx = fmaxf(mx, __shfl_xor_sync(~0u,mx,o));
            float ex = (lane < cnt) ? expf(lg - mx) : 0.f;
            float sm = ex;
            #pragma unroll
            for (int o=16;o;o>>=1) sm += __shfl_xor_sync(~0u,sm,o);
            if (lane < cnt) s_p[w][lane] = ex / sm;
        }
        __syncthreads();
        if (tid < cnt) {
            float p1 = s_p[0][tid], p2 = s_p[1][tid], p3 = s_p[2][tid];
            s_c0[tid] = -lam*p1 + (1.f-lam)*p2;
            s_c1[tid] =  p2 - p1 + (1.f-2.f*lam)*p3;
        }
        __syncthreads();
        const float* vb = g_v + (size_t)b*TT*NXC;
        for (int e=0;e<cnt;e++) {
            const float* vr = vb + (size_t)s_j[e]*NXC;
            a0 = fmaf(s_c0[e], vr[d],       a0);
            a1 = fmaf(s_c1[e], vr[256 + d], a1);
        }
    }
    float ss0 = a0*a0, ss1 = a1*a1;
    #pragma unroll
    for (int o=16;o;o>>=1){ ss0 += __shfl_xor_sync(~0u,ss0,o); ss1 += __shfl_xor_sync(~0u,ss1,o); }
    if ((tid&31)==0){ s_r0[tid>>5]=ss0; s_r1[tid>>5]=ss1; }
    __syncthreads();
    float t0=0.f, t1=0.f;
    #pragma unroll
    for (int q2=0;q2<8;q2++){ t0 += s_r0[q2]; t1 += s_r1[q2]; }
    float r0 = rsqrtf(t0*(1.f/256.f) + EPSC);
    float r1 = rsqrtf(t1*(1.f/256.f) + EPSC);
    float sc = 1.f - g_lam_init;
    float gg = g[d];
    float v0 = a0*r0*gg*sc;
    float v1 = a1*r1*gg*sc;
    size_t base = ((size_t)b*TT + i)*NXC;
    __nv_bfloat16 h0 = __float2bfloat16(v0);
    __nv_bfloat16 h1 = __float2bfloat16(v1);
    g_ah[base + d]       = h0;
    g_al[base + d]       = __float2bfloat16(v0 - __bfloat162float(h0));
    g_ah[base + 256 + d] = h1;
    g_al[base + 256 + d] = __float2bfloat16(v1 - __bfloat162float(h1));
}

// ---------------- launcher (multi-stream fork/join) ----------------------
extern "C" void kernel_launch(void* const* d_in, const int* in_sizes, int n_in,
                              void* d_out, int out_size)
{
    const float* x    = (const float*)d_in[0];
    const float* wq   = (const float*)d_in[1];
    const float* wk   = (const float*)d_in[2];
    const float* wv   = (const float*)d_in[3];
    const float* wo   = (const float*)d_in[4];
    const float* m1   = (const float*)d_in[5];
    const float* m2   = (const float*)d_in[6];
    const float* lq1  = (const float*)d_in[7];
    const float* lk1  = (const float*)d_in[8];
    const float* lq2  = (const float*)d_in[9];
    const float* lk2  = (const float*)d_in[10];
    const float* rmsg = (const float*)d_in[11];
    const int*   lp   = (const int*)d_in[12];
    const int*   rns  = (const int*)d_in[14];
    const int*   lm   = (const int*)d_in[15];
    float* out = (float*)d_out;

    static cudaStream_t s2 = nullptr, s3 = nullptr;
    static cudaEvent_t eS, e0, e2, e3;
    if (!s2) {
        cudaStreamCreateWithFlags(&s2, cudaStreamNonBlocking);
        cudaStreamCreateWithFlags(&s3, cudaStreamNonBlocking);
        cudaEventCreateWithFlags(&eS, cudaEventDisableTiming);
        cudaEventCreateWithFlags(&e0, cudaEventDisableTiming);
        cudaEventCreateWithFlags(&e2, cudaEventDisableTiming);
        cudaEventCreateWithFlags(&e3, cudaEventDisableTiming);
        cudaFuncSetAttribute(k_mma, cudaFuncAttributeMaxDynamicSharedMemorySize, SMEMB);
        cudaFuncSetAttribute(k_w12m, cudaFuncAttributeMaxDynamicSharedMemorySize, W_SMEM);
        cudaFuncSetAttribute(k_mma_out, cudaFuncAttributeMaxDynamicSharedMemorySize, O_SMEM);
    }

    // fork s3: mask chain + scalars (independent of everything else)
    cudaEventRecord(eS, 0);
    cudaStreamWaitEvent(s3, eS, 0);
    k_mask_set<<<BB*TT*KK/256, 256, 0, s3>>>(rns, lq1, lk1, lq2, lk2, lp);
    k_mask<<<(BB*TT)/8, 256, 0, s3>>>(rns);
    cudaEventRecord(e3, s3);

    // main: split, then fork s2 for v-projection (vmean fused in epilogue)
    k_split_all<<<3072, 256>>>(x, wq, wk, wv, wo);
    cudaEventRecord(e0, 0);
    cudaStreamWaitEvent(s2, e0, 0);
    k_mma<<<128, 256, SMEMB, s2>>>(2, nullptr);          // v projection + vmean
    cudaEventRecord(e2, s2);

    // main: qk projection -> landmarks -> w1/w2
    k_mma<<<192, 256, SMEMB>>>(0, nullptr);              // q,k projection
    k_sqsk<<<dim3(384, 2), 128>>>(m1, m2, lm);
    k_w12m<<<192, 256, W_SMEM>>>();

    // join
    cudaStreamWaitEvent(0, e2, 0);
    cudaStreamWaitEvent(0, e3, 0);
    k_sparse<<<BB*TT, 256>>>(rmsg);
    k_mma_out<<<256, 256, O_SMEM>>>(out);
}